// round 12
// baseline (speedup 1.0000x reference)
#include <cuda_runtime.h>
#include <cuda_bf16.h>
#include <math.h>
#include <stdint.h>

// Problem constants (fixed by setup_inputs)
#define BB   1024
#define LL   256
#define HH   512
#define OO   128
#define TENC 200
#define SEQ  100
#define H4   2048
#define K2H  1024
#define BTENC (BB*TENC)
#define BBHH (BB*HH)
#define NCTAS 128

// ======================= helpers =======================
__device__ __forceinline__ uint32_t smem_u32(const void* p) {
    uint32_t a;
    asm("{ .reg .u64 t; cvta.to.shared.u64 t, %1; cvt.u32.u64 %0, t; }" : "=r"(a) : "l"(p));
    return a;
}
__device__ __forceinline__ void ldm_x4(uint32_t* r, uint32_t addr) {
    asm volatile("ldmatrix.sync.aligned.m8n8.x4.shared.b16 {%0,%1,%2,%3}, [%4];"
                 : "=r"(r[0]), "=r"(r[1]), "=r"(r[2]), "=r"(r[3]) : "r"(addr));
}
__device__ __forceinline__ void mma16816(float* d, const uint32_t* a, const uint32_t* b) {
    asm volatile("mma.sync.aligned.m16n8k16.row.col.f32.bf16.bf16.f32 "
                 "{%0,%1,%2,%3}, {%4,%5,%6,%7}, {%8,%9}, {%0,%1,%2,%3};"
                 : "+f"(d[0]), "+f"(d[1]), "+f"(d[2]), "+f"(d[3])
                 : "r"(a[0]), "r"(a[1]), "r"(a[2]), "r"(a[3]), "r"(b[0]), "r"(b[1]));
}
__device__ __forceinline__ void cp16(uint32_t s, const void* g) {
    asm volatile("cp.async.cg.shared.global [%0], [%1], 16;" :: "r"(s), "l"(g));
}
#define CP_COMMIT() asm volatile("cp.async.commit_group;" ::: "memory")
#define CP_WAIT0()  asm volatile("cp.async.wait_group 0;" ::: "memory")
#define CP_WAIT1()  asm volatile("cp.async.wait_group 1;" ::: "memory")

__device__ __forceinline__ uint4 ldcg4(const uint32_t* p) {
    uint4 r;
    asm volatile("ld.global.cg.v4.u32 {%0,%1,%2,%3}, [%4];"
                 : "=r"(r.x), "=r"(r.y), "=r"(r.z), "=r"(r.w) : "l"(p));
    return r;
}
__device__ __forceinline__ uint32_t packf(float h) {
    __nv_bfloat16 hh = __float2bfloat16(h);
    __nv_bfloat16 hl = __float2bfloat16(h - __bfloat162float(hh));
    return (uint32_t)__bfloat16_as_ushort(hh) | ((uint32_t)__bfloat16_as_ushort(hl) << 16);
}
__device__ __forceinline__ float unpackf(uint32_t p) {
    __nv_bfloat16 hi = __ushort_as_bfloat16((unsigned short)(p & 0xFFFFu));
    __nv_bfloat16 lo = __ushort_as_bfloat16((unsigned short)(p >> 16));
    return __bfloat162float(hi) + __bfloat162float(lo);
}
__device__ __forceinline__ float sigf(float x) { return 1.f / (1.f + __expf(-x)); }

// ======================= device scratch =======================
__device__ __align__(16) uint32_t g_Hp[(size_t)(SEQ + 1) * BBHH]; // packed h history; slab 0 = h0
__device__ __align__(16) uint32_t g_Ax[2][BBHH];                  // packed relu(x) side, dbl-buffered
__device__ __align__(16) float g_c[BBHH];
__device__ __align__(16) float g_emb[HH];
__device__ __align__(16) float g_bcat[H4];                        // gate-major [g*HH + j]
__device__ __align__(16) __nv_bfloat16 g_Wb_hi[(size_t)H4 * K2H]; // interleaved rows n'=j*4+g
__device__ __align__(16) __nv_bfloat16 g_Wb_lo[(size_t)H4 * K2H];
__device__ __align__(16) __nv_bfloat16 g_Ws_hi[HH * LL];          // Wseq split [j][k]
__device__ __align__(16) __nv_bfloat16 g_Ws_lo[HH * LL];
__device__ __align__(16) __nv_bfloat16 g_Wo_hi[OO * HH];          // Wout split [o][k]
__device__ __align__(16) __nv_bfloat16 g_Wo_lo[OO * HH];
__device__ __align__(16) __nv_bfloat16 g_Eh[(size_t)BTENC * LL];  // enc_out split
__device__ __align__(16) __nv_bfloat16 g_El[(size_t)BTENC * LL];
__device__ unsigned g_bar_cnt = 0;
__device__ unsigned g_bar_gen = 0;

// ======================= grid barrier (single-wave persistent kernel) =======================
__device__ __forceinline__ void gridbar() {
    __syncthreads();
    if (threadIdx.x == 0) {
        __threadfence();
        unsigned gen = atomicAdd(&g_bar_gen, 0u);
        if (atomicAdd(&g_bar_cnt, 1u) == NCTAS - 1u) {
            atomicExch(&g_bar_cnt, 0u);
            __threadfence();
            atomicAdd(&g_bar_gen, 1u);
        } else {
            while (atomicAdd(&g_bar_gen, 0u) == gen) {}
        }
    }
    __syncthreads();
}

// ======================= 512-thread 32-k stage machinery (y_mma / num_mma, round-6 proven) =======================
// stage layout: A_hi[128][80B] @0, A_lo @10240, B_hi @20480, B_lo @30720; stage = 40960 B.
__device__ __forceinline__ void tile_compute(uint32_t sa, int wm, int wn, int lane, float acc[2][4][4]) {
    #pragma unroll
    for (int kk = 0; kk < 32; kk += 16) {
        uint32_t ah[2][4], al[2][4], bh[2][4], bl[2][4];
        #pragma unroll
        for (int i = 0; i < 2; i++) {
            uint32_t ad = sa + (uint32_t)(wm * 32 + i * 16 + (lane & 15)) * 80
                        + (uint32_t)(kk + (lane >> 4) * 8) * 2;
            ldm_x4(ah[i], ad);
            ldm_x4(al[i], ad + 10240);
        }
        #pragma unroll
        for (int s = 0; s < 2; s++) {
            uint32_t bd = sa + 20480 + (uint32_t)(wn * 32 + s * 16 + (lane >> 4) * 8 + (lane & 7)) * 80
                        + (uint32_t)(kk + ((lane >> 3) & 1) * 8) * 2;
            ldm_x4(bh[s], bd);
            ldm_x4(bl[s], bd + 10240);
        }
        #pragma unroll
        for (int i = 0; i < 2; i++)
            #pragma unroll
            for (int nt = 0; nt < 4; nt++)
                mma16816(acc[i][nt], ah[i], &bh[nt >> 1][(nt & 1) * 2]);
        #pragma unroll
        for (int i = 0; i < 2; i++)
            #pragma unroll
            for (int nt = 0; nt < 4; nt++)
                mma16816(acc[i][nt], ah[i], &bl[nt >> 1][(nt & 1) * 2]);
        #pragma unroll
        for (int i = 0; i < 2; i++)
            #pragma unroll
            for (int nt = 0; nt < 4; nt++)
                mma16816(acc[i][nt], al[i], &bh[nt >> 1][(nt & 1) * 2]);
    }
}

struct ARegs32 { uint4 v[2]; };
__device__ __forceinline__ void store_A32(char* base, int tid, const ARegs32& R) {
    #pragma unroll
    for (int i = 0; i < 2; i++) {
        int idx = tid + i * 512, r = idx >> 3, cg = idx & 7;
        uint4 P = R.v[i];
        uint32_t h0 = __byte_perm(P.x, P.y, 0x5410);
        uint32_t h1 = __byte_perm(P.z, P.w, 0x5410);
        uint32_t l0 = __byte_perm(P.x, P.y, 0x7632);
        uint32_t l1 = __byte_perm(P.z, P.w, 0x7632);
        uint32_t off = (uint32_t)r * 80 + (uint32_t)cg * 8;
        *(uint2*)(base + off) = make_uint2(h0, h1);
        *(uint2*)(base + 10240 + off) = make_uint2(l0, l1);
    }
}

// ======================= step: persistent, M128 tile, 512 threads, K=64, 2-stage =======================
// stage: A_hi[128][144B] @0 (18432), A_lo @18432, B_hi[128][144B] @36864, B_lo @55296; stage = 73728.
#define P_ALO   18432
#define P_BHI   36864
#define P_BLOD  18432
#define P_STAGE 73728
#define P_SMEM  (2 * P_STAGE)

__device__ __forceinline__ void tile_compute64(uint32_t sa, int wm, int wn, int lane, float acc[2][4][4]) {
    #pragma unroll
    for (int kk = 0; kk < 64; kk += 16) {
        uint32_t ah[2][4], al[2][4], bh[2][4], bl[2][4];
        #pragma unroll
        for (int i = 0; i < 2; i++) {
            uint32_t ad = sa + (uint32_t)(wm * 32 + i * 16 + (lane & 15)) * 144
                        + (uint32_t)(kk + (lane >> 4) * 8) * 2;
            ldm_x4(ah[i], ad);
            ldm_x4(al[i], ad + P_ALO);
        }
        #pragma unroll
        for (int s = 0; s < 2; s++) {
            uint32_t bd = sa + P_BHI + (uint32_t)(wn * 32 + s * 16 + (lane >> 4) * 8 + (lane & 7)) * 144
                        + (uint32_t)(kk + ((lane >> 3) & 1) * 8) * 2;
            ldm_x4(bh[s], bd);
            ldm_x4(bl[s], bd + P_BLOD);
        }
        #pragma unroll
        for (int i = 0; i < 2; i++)
            #pragma unroll
            for (int nt = 0; nt < 4; nt++)
                mma16816(acc[i][nt], ah[i], &bh[nt >> 1][(nt & 1) * 2]);
        #pragma unroll
        for (int i = 0; i < 2; i++)
            #pragma unroll
            for (int nt = 0; nt < 4; nt++)
                mma16816(acc[i][nt], ah[i], &bl[nt >> 1][(nt & 1) * 2]);
        #pragma unroll
        for (int i = 0; i < 2; i++)
            #pragma unroll
            for (int nt = 0; nt < 4; nt++)
                mma16816(acc[i][nt], al[i], &bh[nt >> 1][(nt & 1) * 2]);
    }
}

// fused load->split->store; ld.global.cg for cross-CTA persistent state. 128 rows x 64 k.
__device__ __forceinline__ void loadstore_A128(char* base,
                                               const uint32_t* __restrict__ ax,
                                               const uint32_t* __restrict__ hp,
                                               int m0, int k0, int tid) {
    #pragma unroll
    for (int i = 0; i < 4; i++) {
        int idx = tid + i * 512, r = idx >> 4, cg = idx & 15;  // r<128, cg<16
        int gk = k0 + cg * 4;
        const uint32_t* src = (gk < HH) ? (ax + (size_t)(m0 + r) * HH + gk)
                                        : (hp + (size_t)(m0 + r) * HH + (gk - HH));
        uint4 P = ldcg4(src);
        uint32_t h0 = __byte_perm(P.x, P.y, 0x5410);
        uint32_t h1 = __byte_perm(P.z, P.w, 0x5410);
        uint32_t l0 = __byte_perm(P.x, P.y, 0x7632);
        uint32_t l1 = __byte_perm(P.z, P.w, 0x7632);
        uint32_t off = (uint32_t)r * 144 + (uint32_t)cg * 8;
        *(uint2*)(base + off) = make_uint2(h0, h1);
        *(uint2*)(base + P_ALO + off) = make_uint2(l0, l1);
    }
}
__device__ __forceinline__ void issue_B128(uint32_t sb, int tid, int j0, int k0) {
    #pragma unroll
    for (int i = 0; i < 4; i++) {
        int idx = tid + i * 512;                 // [0,2048)
        int half = idx >> 10;                    // 0 = hi, 1 = lo
        int w = idx & 1023;                      // [0,1024)
        int rr = w >> 3, cc = w & 7;             // row<128, 8x16B chunks (128B data/row)
        uint32_t so = (uint32_t)rr * 144 + (uint32_t)cc * 16;
        const __nv_bfloat16* src = half ? g_Wb_lo : g_Wb_hi;
        cp16(sb + P_BHI + (uint32_t)half * P_BLOD + so,
             src + (size_t)(j0 * 4 + rr) * K2H + k0 + cc * 8);
    }
}

__global__ void __launch_bounds__(512, 1) step_persist() {
    extern __shared__ char sm[];
    uint32_t sbase = smem_u32(sm);
    int tid = threadIdx.x, lane = tid & 31, wid = tid >> 5;
    int wm = wid & 3, wn = wid >> 2;
    int j0 = blockIdx.x * 32, m0 = blockIdx.y * 128;
    bool odd = (lane & 1) != 0;

    #pragma unroll 1
    for (int t = 0; t < SEQ; t++) {
        const uint32_t* __restrict__ ax = g_Ax[t & 1];
        const uint32_t* __restrict__ hp = g_Hp + (size_t)t * BBHH;

        float acc[2][4][4];
        #pragma unroll
        for (int i = 0; i < 2; i++)
            #pragma unroll
            for (int nt = 0; nt < 4; nt++)
                #pragma unroll
                for (int q = 0; q < 4; q++) acc[i][nt][q] = 0.f;

        issue_B128(sbase, tid, j0, 0);  CP_COMMIT();
        loadstore_A128(sm, ax, hp, m0, 0, tid);

        #pragma unroll 1
        for (int c = 0; c < 16; c++) {
            CP_WAIT0();
            __syncthreads();
            if (c + 1 < 16) {
                issue_B128(sbase + (uint32_t)((c + 1) & 1) * P_STAGE, tid, j0, (c + 1) * 64);
                CP_COMMIT();
                loadstore_A128(sm + ((c + 1) & 1) * P_STAGE, ax, hp, m0, (c + 1) * 64, tid);
            }
            tile_compute64(sbase + (uint32_t)(c & 1) * P_STAGE, wm, wn, lane, acc);
        }

        // fused LSTM epilogue; lane pairs (l, l^1) exchange gate halves (round-6 proven mapping)
        uint32_t* __restrict__ hpn = g_Hp + (size_t)(t + 1) * BBHH;
        uint32_t* __restrict__ axn = g_Ax[(t + 1) & 1];
        #pragma unroll
        for (int i = 0; i < 2; i++)
            #pragma unroll
            for (int nt = 0; nt < 4; nt++) {
                float s0 = __shfl_xor_sync(0xFFFFFFFFu, acc[i][nt][0], 1);
                float s1 = __shfl_xor_sync(0xFFFFFFFFu, acc[i][nt][1], 1);
                float s2 = __shfl_xor_sync(0xFFFFFFFFu, acc[i][nt][2], 1);
                float s3 = __shfl_xor_sync(0xFFFFFFFFu, acc[i][nt][3], 1);
                int j = j0 + wn * 8 + nt * 2 + ((lane & 3) >> 1);
                int m = m0 + wm * 32 + i * 16 + (lane >> 2) + (odd ? 8 : 0);
                float gi = odd ? s2 : acc[i][nt][0];
                float gf = odd ? s3 : acc[i][nt][1];
                float gg = odd ? acc[i][nt][2] : s0;
                float go = odd ? acc[i][nt][3] : s1;
                gi += g_bcat[j]; gf += g_bcat[HH + j]; gg += g_bcat[2 * HH + j]; go += g_bcat[3 * HH + j];
                size_t o = (size_t)m * HH + j;
                float cn = sigf(gf) * g_c[o] + sigf(gi) * tanhf(gg);
                g_c[o] = cn;
                float h = sigf(go) * tanhf(cn);
                uint32_t p = packf(h);
                hpn[o] = p;
                axn[o] = (h > 0.f) ? p : 0u;
            }

        if (t + 1 < SEQ) gridbar();
    }
}

// ======================= prep kernels =======================
__global__ void prep_w(const float* __restrict__ Wih, const float* __restrict__ Whh,
                       const float* __restrict__ bih, const float* __restrict__ bhh,
                       const float* __restrict__ st, const float* __restrict__ Wemb,
                       const float* __restrict__ bemb) {
    int idx = blockIdx.x * blockDim.x + threadIdx.x;
    if (idx < H4 * K2H) {
        int rn = idx / K2H, k = idx % K2H;
        int j = rn >> 2, g = rn & 3;
        int src = g * HH + j;
        float v = (k < HH) ? Wih[src * HH + k] : Whh[src * HH + (k - HH)];
        __nv_bfloat16 h = __float2bfloat16(v);
        g_Wb_hi[idx] = h;
        g_Wb_lo[idx] = __float2bfloat16(v - __bfloat162float(h));
    }
    if (idx < H4) g_bcat[idx] = bih[idx] + bhh[idx];
    if (blockIdx.x < 64) {  // emb: one warp per j
        int wid = threadIdx.x >> 5, lane = threadIdx.x & 31;
        int j = blockIdx.x * 8 + wid;
        float4 a = ((const float4*)st)[lane];
        float4 w = *(const float4*)&Wemb[j * OO + lane * 4];
        float s = a.x * w.x + a.y * w.y + a.z * w.z + a.w * w.w;
        #pragma unroll
        for (int o = 16; o; o >>= 1) s += __shfl_xor_sync(0xFFFFFFFFu, s, o);
        if (lane == 0) g_emb[j] = bemb[j] + s;
    }
}
__global__ void prep2E(const float* __restrict__ E) {
    size_t i = (size_t)blockIdx.x * blockDim.x + threadIdx.x;
    if (i < (size_t)BTENC * LL / 4) {
        float4 v = ((const float4*)E)[i];
        __nv_bfloat16 hx = __float2bfloat16(v.x), hy = __float2bfloat16(v.y);
        __nv_bfloat16 hz = __float2bfloat16(v.z), hw = __float2bfloat16(v.w);
        __nv_bfloat16 lx = __float2bfloat16(v.x - __bfloat162float(hx));
        __nv_bfloat16 ly = __float2bfloat16(v.y - __bfloat162float(hy));
        __nv_bfloat16 lz = __float2bfloat16(v.z - __bfloat162float(hz));
        __nv_bfloat16 lw = __float2bfloat16(v.w - __bfloat162float(hw));
        uint32_t h0 = (uint32_t)__bfloat16_as_ushort(hx) | ((uint32_t)__bfloat16_as_ushort(hy) << 16);
        uint32_t h1 = (uint32_t)__bfloat16_as_ushort(hz) | ((uint32_t)__bfloat16_as_ushort(hw) << 16);
        uint32_t l0 = (uint32_t)__bfloat16_as_ushort(lx) | ((uint32_t)__bfloat16_as_ushort(ly) << 16);
        uint32_t l1 = (uint32_t)__bfloat16_as_ushort(lz) | ((uint32_t)__bfloat16_as_ushort(lw) << 16);
        ((uint2*)g_Eh)[i] = make_uint2(h0, h1);
        ((uint2*)g_El)[i] = make_uint2(l0, l1);
    }
}
__global__ void prep2W(const float* __restrict__ Wseq, const float* __restrict__ Wout) {
    int i = blockIdx.x * blockDim.x + threadIdx.x;
    if (i < HH * LL) {
        float v = Wseq[i];
        __nv_bfloat16 h = __float2bfloat16(v);
        g_Ws_hi[i] = h;
        g_Ws_lo[i] = __float2bfloat16(v - __bfloat162float(h));
    }
    if (i < OO * HH) {
        float v = Wout[i];
        __nv_bfloat16 h = __float2bfloat16(v);
        g_Wo_hi[i] = h;
        g_Wo_lo[i] = __float2bfloat16(v - __bfloat162float(h));
    }
}
// seed g_Ax[0][m*HH+j] = packf(relu(emb[j]))
__global__ void seed_ax() {
    int i = blockIdx.x * blockDim.x + threadIdx.x;
    if (i < BBHH) {
        float e = g_emb[i & (HH - 1)];
        g_Ax[0][i] = (e > 0.f) ? packf(e) : 0u;
    }
}

// ======================= init: h0/c0 + Hp slab 0 =======================
__global__ void __launch_bounds__(256) init_kernel(
    const float* __restrict__ eh, const float* __restrict__ W1, const float* __restrict__ b1,
    const float* __restrict__ W2, const float* __restrict__ b2) {
    __shared__ float As[64][17], B1s[64][17], B2s[64][17];
    int m0 = blockIdx.y * 64, j0 = blockIdx.x * 64;
    int tid = threadIdx.x, tm = tid >> 4, tj = tid & 15;
    float acc1[4][4] = {}, acc2[4][4] = {};
    for (int k0 = 0; k0 < LL; k0 += 16) {
        int r = tid >> 2, c = (tid & 3) * 4;
        float4 va = *(const float4*)&eh[(m0 + r) * LL + k0 + c];
        As[r][c] = va.x; As[r][c+1] = va.y; As[r][c+2] = va.z; As[r][c+3] = va.w;
        float4 v1 = *(const float4*)&W1[(j0 + r) * LL + k0 + c];
        B1s[r][c] = v1.x; B1s[r][c+1] = v1.y; B1s[r][c+2] = v1.z; B1s[r][c+3] = v1.w;
        float4 v2 = *(const float4*)&W2[(j0 + r) * LL + k0 + c];
        B2s[r][c] = v2.x; B2s[r][c+1] = v2.y; B2s[r][c+2] = v2.z; B2s[r][c+3] = v2.w;
        __syncthreads();
        #pragma unroll
        for (int kk = 0; kk < 16; kk++) {
            float a[4], u[4], v[4];
            #pragma unroll
            for (int i = 0; i < 4; i++) a[i] = As[tm * 4 + i][kk];
            #pragma unroll
            for (int jv = 0; jv < 4; jv++) { u[jv] = B1s[tj + jv * 16][kk]; v[jv] = B2s[tj + jv * 16][kk]; }
            #pragma unroll
            for (int i = 0; i < 4; i++)
                #pragma unroll
                for (int jv = 0; jv < 4; jv++) { acc1[i][jv] += a[i] * u[jv]; acc2[i][jv] += a[i] * v[jv]; }
        }
        __syncthreads();
    }
    #pragma unroll
    for (int i = 0; i < 4; i++)
        #pragma unroll
        for (int jv = 0; jv < 4; jv++) {
            int m = m0 + tm * 4 + i, j = j0 + tj + jv * 16;
            float h0 = acc1[i][jv] + b1[j]; h0 = h0 > 0.f ? h0 : 0.01f * h0;
            float c0 = acc2[i][jv] + b2[j]; c0 = c0 > 0.f ? c0 : 0.01f * c0;
            size_t o = (size_t)m * HH + j;
            g_c[o] = c0;
            g_Hp[o] = packf(h0);                       // slab 0
        }
}

// ======================= y projection: MMA, packed A, pre-split Wout (round-6 proven) =======================
__device__ __forceinline__ void y_issue_B(uint32_t sb, int tid, int k0) {
    int r = tid >> 2, cc = tid & 3;
    uint32_t so = (uint32_t)r * 80 + (uint32_t)cc * 16;
    size_t gb = (size_t)r * HH + k0 + cc * 8;
    cp16(sb + 20480 + so, g_Wo_hi + gb);
    cp16(sb + 30720 + so, g_Wo_lo + gb);
}
__device__ __forceinline__ void y_load_A(const uint32_t* __restrict__ hp,
                                         int m0, int k0, int tid, ARegs32& R) {
    #pragma unroll
    for (int i = 0; i < 2; i++) {
        int idx = tid + i * 512, r = idx >> 3, cg = idx & 7;
        R.v[i] = *(const uint4*)(hp + (size_t)(m0 + r) * HH + k0 + cg * 4);
    }
}

__global__ void __launch_bounds__(512, 1) y_mma(const float* __restrict__ b_out,
                                                float* __restrict__ out_dec) {
    extern __shared__ char sm[];
    uint32_t sbase = smem_u32(sm);
    int tid = threadIdx.x, lane = tid & 31, wid = tid >> 5;
    int wm = wid & 3, wn = wid >> 2;
    int t = blockIdx.y, m0 = blockIdx.x * 128;
    const uint32_t* __restrict__ hp = g_Hp + (size_t)(t + 1) * BBHH;

    float acc[2][4][4];
    #pragma unroll
    for (int i = 0; i < 2; i++)
        #pragma unroll
        for (int nt = 0; nt < 4; nt++)
            #pragma unroll
            for (int q = 0; q < 4; q++) acc[i][nt][q] = 0.f;

    y_issue_B(sbase, tid, 0);  CP_COMMIT();
    y_issue_B(sbase + 40960u, tid, 32); CP_COMMIT();
    ARegs32 R;
    y_load_A(hp, m0, 0, tid, R);

    #pragma unroll 1
    for (int c = 0; c < 16; c++) {
        store_A32(sm + (c % 3) * 40960, tid, R);
        if (c == 15) { CP_WAIT0(); } else { CP_WAIT1(); }
        __syncthreads();
        if (c + 2 < 16) { y_issue_B(sbase + (uint32_t)((c + 2) % 3) * 40960u, tid, (c + 2) * 32); CP_COMMIT(); }
        if (c + 1 < 16) y_load_A(hp, m0, (c + 1) * 32, tid, R);
        tile_compute(sbase + (uint32_t)(c % 3) * 40960u, wm, wn, lane, acc);
    }

    #pragma unroll
    for (int i = 0; i < 2; i++)
        #pragma unroll
        for (int nt = 0; nt < 4; nt++)
            #pragma unroll
            for (int q = 0; q < 4; q++) {
                int m = m0 + wm * 32 + i * 16 + (lane >> 2) + (q >> 1) * 8;
                int o = wn * 32 + nt * 8 + (lane & 3) * 2 + (q & 1);
                out_dec[((size_t)m * SEQ + t) * OO + o] = acc[i][nt][q] + b_out[o];
            }
}

__global__ void hc_kernel(float* __restrict__ out_h, float* __restrict__ out_c) {
    int i = blockIdx.x * blockDim.x + threadIdx.x;
    if (i < BBHH) {
        out_h[i] = unpackf(g_Hp[(size_t)SEQ * BBHH + i]);
        out_c[i] = g_c[i];
    }
}

// ======================= num head: MMA pipeline + fused 2nd layer (round-6 proven) =======================
__device__ __forceinline__ void num_issue(uint32_t sbase, int stage, int tid, int m0, int chunk) {
    int nq = chunk >> 3, k0 = (chunk & 7) * 32;
    uint32_t sb = sbase + (uint32_t)stage * 40960u;
    int r = tid >> 2, cc = tid & 3;
    uint32_t so = (uint32_t)r * 80 + (uint32_t)cc * 16;
    size_t ga = (size_t)(m0 + r) * LL + k0 + cc * 8;
    size_t gb = (size_t)(nq * 128 + r) * LL + k0 + cc * 8;
    cp16(sb + so,         g_Eh + ga);
    cp16(sb + 10240 + so, g_El + ga);
    cp16(sb + 20480 + so, g_Ws_hi + gb);
    cp16(sb + 30720 + so, g_Ws_lo + gb);
}

#define NUM_SMEM (122880 + 2048)

__global__ void __launch_bounds__(512, 1) num_mma(
    const float* __restrict__ bseq, const float* __restrict__ w2,
    const float* __restrict__ b2, float* __restrict__ outnum) {
    extern __shared__ char sm[];
    uint32_t sbase = smem_u32(sm);
    int tid = threadIdx.x, lane = tid & 31, wid = tid >> 5;
    int wm = wid & 3, wn = wid >> 2;
    int m0 = blockIdx.x * 128;

    float acc[2][4][4];
    #pragma unroll
    for (int i = 0; i < 2; i++)
        #pragma unroll
        for (int nt = 0; nt < 4; nt++)
            #pragma unroll
            for (int q = 0; q < 4; q++) acc[i][nt][q] = 0.f;
    float s[4] = {0.f, 0.f, 0.f, 0.f};

    num_issue(sbase, 0, tid, m0, 0); CP_COMMIT();
    num_issue(sbase, 1, tid, m0, 1); CP_COMMIT();
    #pragma unroll 1
    for (int c = 0; c < 32; c++) {
        if (c == 31) { CP_WAIT0(); } else { CP_WAIT1(); }
        __syncthreads();
        if (c + 2 < 32) { num_issue(sbase, (c + 2) % 3, tid, m0, c + 2); CP_COMMIT(); }
        tile_compute(sbase + (uint32_t)(c % 3) * 40960u, wm, wn, lane, acc);
        if ((c & 7) == 7) {
            int nq = c >> 3;
            #pragma unroll
            for (int i = 0; i < 2; i++)
                #pragma unroll
                for (int nt = 0; nt < 4; nt++)
                    #pragma unroll
                    for (int q = 0; q < 4; q++) {
                        int rh = q >> 1, cc2 = q & 1;
                        int j = nq * 128 + wn * 32 + nt * 8 + (lane & 3) * 2 + cc2;
                        float v = acc[i][nt][q] + __ldg(&bseq[j]);
                        v = v > 0.f ? v : 0.01f * v;
                        s[i * 2 + rh] += v * __ldg(&w2[j]);
                        acc[i][nt][q] = 0.f;
                    }
        }
    }
    #pragma unroll
    for (int q = 0; q < 4; q++) {
        s[q] += __shfl_xor_sync(0xFFFFFFFFu, s[q], 1);
        s[q] += __shfl_xor_sync(0xFFFFFFFFu, s[q], 2);
    }
    float* P = (float*)(sm + 122880);
    if ((lane & 3) == 0) {
        #pragma unroll
        for (int i = 0; i < 2; i++)
            #pragma unroll
            for (int rh = 0; rh < 2; rh++) {
                int ml = wm * 32 + i * 16 + rh * 8 + (lane >> 2);
                P[wn * 128 + ml] = s[i * 2 + rh];
            }
    }
    __syncthreads();
    if (tid < 128) {
        float v = P[tid] + P[128 + tid] + P[256 + tid] + P[384 + tid] + b2[0];
        outnum[m0 + tid] = v > 0.f ? v : 0.f;
    }
}

// ======================= launch =======================
extern "C" void kernel_launch(void* const* d_in, const int* in_sizes, int n_in,
                              void* d_out, int out_size) {
    const float* enc_out = (const float*)d_in[0];
    const float* enc_hid = (const float*)d_in[1];
    const float* start   = (const float*)d_in[2];
    const float* W1   = (const float*)d_in[3];
    const float* b1   = (const float*)d_in[4];
    const float* W2   = (const float*)d_in[5];
    const float* b2   = (const float*)d_in[6];
    const float* Wemb = (const float*)d_in[7];
    const float* bemb = (const float*)d_in[8];
    const float* Wih  = (const float*)d_in[9];
    const float* Whh  = (const float*)d_in[10];
    const float* bih  = (const float*)d_in[11];
    const float* bhh  = (const float*)d_in[12];
    const float* Wout = (const float*)d_in[13];
    const float* bout = (const float*)d_in[14];
    const float* Wseq = (const float*)d_in[15];
    const float* bseq = (const float*)d_in[16];
    const float* Wsq2 = (const float*)d_in[17];
    const float* bsq2 = (const float*)d_in[18];
    // d_in[19] = seq_len (constant 100; hardcoded)

    float* out = (float*)d_out;
    float* out_dec = out;                           // [B, SEQ, O]
    float* out_h   = out + (size_t)BB * SEQ * OO;   // [1, B, H]
    float* out_c   = out_h + (size_t)BBHH;          // [1, B, H]
    float* out_num = out_c + (size_t)BBHH;          // [B, TENC, 1]

    cudaFuncSetAttribute(step_persist, cudaFuncAttributeMaxDynamicSharedMemorySize, P_SMEM);
    cudaFuncSetAttribute(y_mma, cudaFuncAttributeMaxDynamicSharedMemorySize, 122880);
    cudaFuncSetAttribute(num_mma, cudaFuncAttributeMaxDynamicSharedMemorySize, NUM_SMEM);

    prep_w<<<(H4 * K2H + 255) / 256, 256>>>(Wih, Whh, bih, bhh, start, Wemb, bemb);
    prep2E<<<(int)(((size_t)BTENC * LL / 4 + 255) / 256), 256>>>(enc_out);
    prep2W<<<(HH * LL + 255) / 256, 256>>>(Wseq, Wout);
    init_kernel<<<dim3(HH / 64, BB / 64), 256>>>(enc_hid, W1, b1, W2, b2);
    seed_ax<<<(BBHH + 255) / 256, 256>>>();

    step_persist<<<dim3(16, 8), 512, P_SMEM>>>();

    y_mma<<<dim3(BB / 128, SEQ), 512, 122880>>>(bout, out_dec);
    hc_kernel<<<(BBHH + 255) / 256, 256>>>(out_h, out_c);
    num_mma<<<BTENC / 128, 512, NUM_SMEM>>>(bseq, Wsq2, bsq2, out_num);
}

// round 13
// speedup vs baseline: 1.1829x; 1.1829x over previous
#include <cuda_runtime.h>
#include <cuda_bf16.h>
#include <math.h>
#include <stdint.h>

// Problem constants (fixed by setup_inputs)
#define BB   1024
#define LL   256
#define HH   512
#define OO   128
#define TENC 200
#define SEQ  100
#define H4   2048
#define K2H  1024
#define BTENC (BB*TENC)
#define BBHH (BB*HH)
#define NCTAS 256

// ======================= helpers =======================
__device__ __forceinline__ uint32_t smem_u32(const void* p) {
    uint32_t a;
    asm("{ .reg .u64 t; cvta.to.shared.u64 t, %1; cvt.u32.u64 %0, t; }" : "=r"(a) : "l"(p));
    return a;
}
__device__ __forceinline__ void ldm_x4(uint32_t* r, uint32_t addr) {
    asm volatile("ldmatrix.sync.aligned.m8n8.x4.shared.b16 {%0,%1,%2,%3}, [%4];"
                 : "=r"(r[0]), "=r"(r[1]), "=r"(r[2]), "=r"(r[3]) : "r"(addr));
}
__device__ __forceinline__ void mma16816(float* d, const uint32_t* a, const uint32_t* b) {
    asm volatile("mma.sync.aligned.m16n8k16.row.col.f32.bf16.bf16.f32 "
                 "{%0,%1,%2,%3}, {%4,%5,%6,%7}, {%8,%9}, {%0,%1,%2,%3};"
                 : "+f"(d[0]), "+f"(d[1]), "+f"(d[2]), "+f"(d[3])
                 : "r"(a[0]), "r"(a[1]), "r"(a[2]), "r"(a[3]), "r"(b[0]), "r"(b[1]));
}
__device__ __forceinline__ void cp16(uint32_t s, const void* g) {
    asm volatile("cp.async.cg.shared.global [%0], [%1], 16;" :: "r"(s), "l"(g));
}
#define CP_COMMIT() asm volatile("cp.async.commit_group;" ::: "memory")
#define CP_WAIT0()  asm volatile("cp.async.wait_group 0;" ::: "memory")
#define CP_WAIT1()  asm volatile("cp.async.wait_group 1;" ::: "memory")

__device__ __forceinline__ uint4 ldcg4(const uint32_t* p) {
    uint4 r;
    asm volatile("ld.global.cg.v4.u32 {%0,%1,%2,%3}, [%4];"
                 : "=r"(r.x), "=r"(r.y), "=r"(r.z), "=r"(r.w) : "l"(p));
    return r;
}
__device__ __forceinline__ uint32_t packf(float h) {
    __nv_bfloat16 hh = __float2bfloat16(h);
    __nv_bfloat16 hl = __float2bfloat16(h - __bfloat162float(hh));
    return (uint32_t)__bfloat16_as_ushort(hh) | ((uint32_t)__bfloat16_as_ushort(hl) << 16);
}
__device__ __forceinline__ float unpackf(uint32_t p) {
    __nv_bfloat16 hi = __ushort_as_bfloat16((unsigned short)(p & 0xFFFFu));
    __nv_bfloat16 lo = __ushort_as_bfloat16((unsigned short)(p >> 16));
    return __bfloat162float(hi) + __bfloat162float(lo);
}
__device__ __forceinline__ float sigf(float x) { return 1.f / (1.f + __expf(-x)); }

// ======================= device scratch =======================
__device__ __align__(16) uint32_t g_Hp[(size_t)(SEQ + 1) * BBHH]; // packed h history; slab 0 = h0
__device__ __align__(16) uint32_t g_Ax[2][BBHH];                  // packed relu(x) side, dbl-buffered
__device__ __align__(16) float g_c[BBHH];
__device__ __align__(16) float g_emb[HH];
__device__ __align__(16) float g_bcat[H4];                        // gate-major [g*HH + j]
__device__ __align__(16) __nv_bfloat16 g_Wb_hi[(size_t)H4 * K2H]; // interleaved rows n'=j*4+g
__device__ __align__(16) __nv_bfloat16 g_Wb_lo[(size_t)H4 * K2H];
__device__ __align__(16) __nv_bfloat16 g_Ws_hi[HH * LL];          // Wseq split [j][k]
__device__ __align__(16) __nv_bfloat16 g_Ws_lo[HH * LL];
__device__ __align__(16) __nv_bfloat16 g_Wo_hi[OO * HH];          // Wout split [o][k]
__device__ __align__(16) __nv_bfloat16 g_Wo_lo[OO * HH];
__device__ __align__(16) __nv_bfloat16 g_Eh[(size_t)BTENC * LL];  // enc_out split
__device__ __align__(16) __nv_bfloat16 g_El[(size_t)BTENC * LL];
__device__ unsigned g_bar_cnt = 0;
__device__ unsigned g_bar_gen = 0;

// ======================= grid barrier: volatile-poll + nanosleep backoff =======================
__device__ __forceinline__ void gridbar() {
    __syncthreads();
    if (threadIdx.x == 0) {
        __threadfence();
        volatile unsigned* vgen = (volatile unsigned*)&g_bar_gen;
        unsigned gen = *vgen;
        if (atomicAdd(&g_bar_cnt, 1u) == NCTAS - 1u) {
            g_bar_cnt = 0u;                 // only the releaser writes; next arrivals are post-release
            __threadfence();
            atomicAdd(&g_bar_gen, 1u);
        } else {
            while (*vgen == gen) { __nanosleep(64); }
        }
    }
    __syncthreads();
}

// ======================= 512-thread 32-k stage machinery (y_mma / num_mma, round-6 proven) =======================
// stage layout: A_hi[128][80B] @0, A_lo @10240, B_hi @20480, B_lo @30720; stage = 40960 B.
__device__ __forceinline__ void tile_compute(uint32_t sa, int wm, int wn, int lane, float acc[2][4][4]) {
    #pragma unroll
    for (int kk = 0; kk < 32; kk += 16) {
        uint32_t ah[2][4], al[2][4], bh[2][4], bl[2][4];
        #pragma unroll
        for (int i = 0; i < 2; i++) {
            uint32_t ad = sa + (uint32_t)(wm * 32 + i * 16 + (lane & 15)) * 80
                        + (uint32_t)(kk + (lane >> 4) * 8) * 2;
            ldm_x4(ah[i], ad);
            ldm_x4(al[i], ad + 10240);
        }
        #pragma unroll
        for (int s = 0; s < 2; s++) {
            uint32_t bd = sa + 20480 + (uint32_t)(wn * 32 + s * 16 + (lane >> 4) * 8 + (lane & 7)) * 80
                        + (uint32_t)(kk + ((lane >> 3) & 1) * 8) * 2;
            ldm_x4(bh[s], bd);
            ldm_x4(bl[s], bd + 10240);
        }
        #pragma unroll
        for (int i = 0; i < 2; i++)
            #pragma unroll
            for (int nt = 0; nt < 4; nt++)
                mma16816(acc[i][nt], ah[i], &bh[nt >> 1][(nt & 1) * 2]);
        #pragma unroll
        for (int i = 0; i < 2; i++)
            #pragma unroll
            for (int nt = 0; nt < 4; nt++)
                mma16816(acc[i][nt], ah[i], &bl[nt >> 1][(nt & 1) * 2]);
        #pragma unroll
        for (int i = 0; i < 2; i++)
            #pragma unroll
            for (int nt = 0; nt < 4; nt++)
                mma16816(acc[i][nt], al[i], &bh[nt >> 1][(nt & 1) * 2]);
    }
}

struct ARegs32 { uint4 v[2]; };
__device__ __forceinline__ void store_A32(char* base, int tid, const ARegs32& R) {
    #pragma unroll
    for (int i = 0; i < 2; i++) {
        int idx = tid + i * 512, r = idx >> 3, cg = idx & 7;
        uint4 P = R.v[i];
        uint32_t h0 = __byte_perm(P.x, P.y, 0x5410);
        uint32_t h1 = __byte_perm(P.z, P.w, 0x5410);
        uint32_t l0 = __byte_perm(P.x, P.y, 0x7632);
        uint32_t l1 = __byte_perm(P.z, P.w, 0x7632);
        uint32_t off = (uint32_t)r * 80 + (uint32_t)cg * 8;
        *(uint2*)(base + off) = make_uint2(h0, h1);
        *(uint2*)(base + 10240 + off) = make_uint2(l0, l1);
    }
}

// ======================= step: M64 tile, K=64 chunks, 2-stage, 2 CTAs/SM, persistent (round-11 proven) =======================
// stage: A_hi[64][144B] @0 (9216), A_lo @9216, B_hi[128][144B] @18432 (18432), B_lo @36864; stage = 55296.
#define S2_ALO   9216
#define S2_BHI   18432
#define S2_BLOD  18432
#define S2_STAGE 55296
#define S2_SMEM  (2 * S2_STAGE)

__device__ __forceinline__ void tile_compute64(uint32_t sa, int wm, int wn, int lane, float acc[2][4][4]) {
    #pragma unroll
    for (int kk = 0; kk < 64; kk += 16) {
        uint32_t ah[2][4], al[2][4], bh[2][4], bl[2][4];
        #pragma unroll
        for (int i = 0; i < 2; i++) {
            uint32_t ad = sa + (uint32_t)(wm * 32 + i * 16 + (lane & 15)) * 144
                        + (uint32_t)(kk + (lane >> 4) * 8) * 2;
            ldm_x4(ah[i], ad);
            ldm_x4(al[i], ad + S2_ALO);
        }
        #pragma unroll
        for (int s = 0; s < 2; s++) {
            uint32_t bd = sa + S2_BHI + (uint32_t)(wn * 32 + s * 16 + (lane >> 4) * 8 + (lane & 7)) * 144
                        + (uint32_t)(kk + ((lane >> 3) & 1) * 8) * 2;
            ldm_x4(bh[s], bd);
            ldm_x4(bl[s], bd + S2_BLOD);
        }
        #pragma unroll
        for (int i = 0; i < 2; i++)
            #pragma unroll
            for (int nt = 0; nt < 4; nt++)
                mma16816(acc[i][nt], ah[i], &bh[nt >> 1][(nt & 1) * 2]);
        #pragma unroll
        for (int i = 0; i < 2; i++)
            #pragma unroll
            for (int nt = 0; nt < 4; nt++)
                mma16816(acc[i][nt], ah[i], &bl[nt >> 1][(nt & 1) * 2]);
        #pragma unroll
        for (int i = 0; i < 2; i++)
            #pragma unroll
            for (int nt = 0; nt < 4; nt++)
                mma16816(acc[i][nt], al[i], &bh[nt >> 1][(nt & 1) * 2]);
    }
}

// fused load->split->store; ld.global.cg (L2-only) for cross-CTA persistent state
__device__ __forceinline__ void loadstore_A64(char* base,
                                              const uint32_t* __restrict__ ax,
                                              const uint32_t* __restrict__ hp,
                                              int m0, int k0, int tid) {
    #pragma unroll
    for (int i = 0; i < 4; i++) {
        int idx = tid + i * 256, r = idx >> 4, cg = idx & 15;  // r<64, cg<16
        int gk = k0 + cg * 4;
        const uint32_t* src = (gk < HH) ? (ax + (size_t)(m0 + r) * HH + gk)
                                        : (hp + (size_t)(m0 + r) * HH + (gk - HH));
        uint4 P = ldcg4(src);
        uint32_t h0 = __byte_perm(P.x, P.y, 0x5410);
        uint32_t h1 = __byte_perm(P.z, P.w, 0x5410);
        uint32_t l0 = __byte_perm(P.x, P.y, 0x7632);
        uint32_t l1 = __byte_perm(P.z, P.w, 0x7632);
        uint32_t off = (uint32_t)r * 144 + (uint32_t)cg * 8;
        *(uint2*)(base + off) = make_uint2(h0, h1);
        *(uint2*)(base + S2_ALO + off) = make_uint2(l0, l1);
    }
}
__device__ __forceinline__ void issue_B64(uint32_t sb, int tid, int j0, int k0) {
    #pragma unroll
    for (int i = 0; i < 8; i++) {
        int idx = tid + i * 256;                 // [0,2048)
        int half = idx >> 10;                    // 0 = hi, 1 = lo
        int w = idx & 1023;                      // [0,1024)
        int rr = w >> 3, cc = w & 7;             // row<128, 8x16B chunks (128B data/row)
        uint32_t so = (uint32_t)rr * 144 + (uint32_t)cc * 16;
        const __nv_bfloat16* src = half ? g_Wb_lo : g_Wb_hi;
        cp16(sb + S2_BHI + (uint32_t)half * S2_BLOD + so,
             src + (size_t)(j0 * 4 + rr) * K2H + k0 + cc * 8);
    }
}

__global__ void __launch_bounds__(256, 2) step_persist() {
    extern __shared__ char sm[];
    uint32_t sbase = smem_u32(sm);
    int tid = threadIdx.x, lane = tid & 31, wid = tid >> 5;
    int wm = wid & 1, wn = wid >> 1;
    int j0 = blockIdx.x * 32, m0 = blockIdx.y * 64;
    bool odd = (lane & 1) != 0;

    #pragma unroll 1
    for (int t = 0; t < SEQ; t++) {
        const uint32_t* __restrict__ ax = g_Ax[t & 1];
        const uint32_t* __restrict__ hp = g_Hp + (size_t)t * BBHH;

        float acc[2][4][4];
        #pragma unroll
        for (int i = 0; i < 2; i++)
            #pragma unroll
            for (int nt = 0; nt < 4; nt++)
                #pragma unroll
                for (int q = 0; q < 4; q++) acc[i][nt][q] = 0.f;

        issue_B64(sbase, tid, j0, 0);  CP_COMMIT();
        loadstore_A64(sm, ax, hp, m0, 0, tid);

        #pragma unroll 1
        for (int c = 0; c < 16; c++) {
            CP_WAIT0();
            __syncthreads();
            if (c + 1 < 16) {
                issue_B64(sbase + (uint32_t)((c + 1) & 1) * S2_STAGE, tid, j0, (c + 1) * 64);
                CP_COMMIT();
                loadstore_A64(sm + ((c + 1) & 1) * S2_STAGE, ax, hp, m0, (c + 1) * 64, tid);
            }
            tile_compute64(sbase + (uint32_t)(c & 1) * S2_STAGE, wm, wn, lane, acc);
        }

        // fused LSTM epilogue; lane pairs (l, l^1) exchange gate halves (verified R4-R11), libm tanhf
        uint32_t* __restrict__ hpn = g_Hp + (size_t)(t + 1) * BBHH;
        uint32_t* __restrict__ axn = g_Ax[(t + 1) & 1];
        #pragma unroll
        for (int i = 0; i < 2; i++)
            #pragma unroll
            for (int nt = 0; nt < 4; nt++) {
                float s0 = __shfl_xor_sync(0xFFFFFFFFu, acc[i][nt][0], 1);
                float s1 = __shfl_xor_sync(0xFFFFFFFFu, acc[i][nt][1], 1);
                float s2 = __shfl_xor_sync(0xFFFFFFFFu, acc[i][nt][2], 1);
                float s3 = __shfl_xor_sync(0xFFFFFFFFu, acc[i][nt][3], 1);
                int j = j0 + wn * 8 + nt * 2 + ((lane & 3) >> 1);
                int m = m0 + wm * 32 + i * 16 + (lane >> 2) + (odd ? 8 : 0);
                float gi = odd ? s2 : acc[i][nt][0];
                float gf = odd ? s3 : acc[i][nt][1];
                float gg = odd ? acc[i][nt][2] : s0;
                float go = odd ? acc[i][nt][3] : s1;
                gi += g_bcat[j]; gf += g_bcat[HH + j]; gg += g_bcat[2 * HH + j]; go += g_bcat[3 * HH + j];
                size_t o = (size_t)m * HH + j;
                float cn = sigf(gf) * g_c[o] + sigf(gi) * tanhf(gg);
                g_c[o] = cn;
                float h = sigf(go) * tanhf(cn);
                uint32_t p = packf(h);
                hpn[o] = p;
                axn[o] = (h > 0.f) ? p : 0u;
            }

        if (t + 1 < SEQ) gridbar();
    }
}

// ======================= prep kernels =======================
__global__ void prep_w(const float* __restrict__ Wih, const float* __restrict__ Whh,
                       const float* __restrict__ bih, const float* __restrict__ bhh,
                       const float* __restrict__ st, const float* __restrict__ Wemb,
                       const float* __restrict__ bemb) {
    int idx = blockIdx.x * blockDim.x + threadIdx.x;
    if (idx < H4 * K2H) {
        int rn = idx / K2H, k = idx % K2H;
        int j = rn >> 2, g = rn & 3;
        int src = g * HH + j;
        float v = (k < HH) ? Wih[src * HH + k] : Whh[src * HH + (k - HH)];
        __nv_bfloat16 h = __float2bfloat16(v);
        g_Wb_hi[idx] = h;
        g_Wb_lo[idx] = __float2bfloat16(v - __bfloat162float(h));
    }
    if (idx < H4) g_bcat[idx] = bih[idx] + bhh[idx];
    if (blockIdx.x < 64) {  // emb: one warp per j
        int wid = threadIdx.x >> 5, lane = threadIdx.x & 31;
        int j = blockIdx.x * 8 + wid;
        float4 a = ((const float4*)st)[lane];
        float4 w = *(const float4*)&Wemb[j * OO + lane * 4];
        float s = a.x * w.x + a.y * w.y + a.z * w.z + a.w * w.w;
        #pragma unroll
        for (int o = 16; o; o >>= 1) s += __shfl_xor_sync(0xFFFFFFFFu, s, o);
        if (lane == 0) g_emb[j] = bemb[j] + s;
    }
}
__global__ void prep2E(const float* __restrict__ E) {
    size_t i = (size_t)blockIdx.x * blockDim.x + threadIdx.x;
    if (i < (size_t)BTENC * LL / 4) {
        float4 v = ((const float4*)E)[i];
        __nv_bfloat16 hx = __float2bfloat16(v.x), hy = __float2bfloat16(v.y);
        __nv_bfloat16 hz = __float2bfloat16(v.z), hw = __float2bfloat16(v.w);
        __nv_bfloat16 lx = __float2bfloat16(v.x - __bfloat162float(hx));
        __nv_bfloat16 ly = __float2bfloat16(v.y - __bfloat162float(hy));
        __nv_bfloat16 lz = __float2bfloat16(v.z - __bfloat162float(hz));
        __nv_bfloat16 lw = __float2bfloat16(v.w - __bfloat162float(hw));
        uint32_t h0 = (uint32_t)__bfloat16_as_ushort(hx) | ((uint32_t)__bfloat16_as_ushort(hy) << 16);
        uint32_t h1 = (uint32_t)__bfloat16_as_ushort(hz) | ((uint32_t)__bfloat16_as_ushort(hw) << 16);
        uint32_t l0 = (uint32_t)__bfloat16_as_ushort(lx) | ((uint32_t)__bfloat16_as_ushort(ly) << 16);
        uint32_t l1 = (uint32_t)__bfloat16_as_ushort(lz) | ((uint32_t)__bfloat16_as_ushort(lw) << 16);
        ((uint2*)g_Eh)[i] = make_uint2(h0, h1);
        ((uint2*)g_El)[i] = make_uint2(l0, l1);
    }
}
__global__ void prep2W(const float* __restrict__ Wseq, const float* __restrict__ Wout) {
    int i = blockIdx.x * blockDim.x + threadIdx.x;
    if (i < HH * LL) {
        float v = Wseq[i];
        __nv_bfloat16 h = __float2bfloat16(v);
        g_Ws_hi[i] = h;
        g_Ws_lo[i] = __float2bfloat16(v - __bfloat162float(h));
    }
    if (i < OO * HH) {
        float v = Wout[i];
        __nv_bfloat16 h = __float2bfloat16(v);
        g_Wo_hi[i] = h;
        g_Wo_lo[i] = __float2bfloat16(v - __bfloat162float(h));
    }
}
// seed g_Ax[0][m*HH+j] = packf(relu(emb[j]))
__global__ void seed_ax() {
    int i = blockIdx.x * blockDim.x + threadIdx.x;
    if (i < BBHH) {
        float e = g_emb[i & (HH - 1)];
        g_Ax[0][i] = (e > 0.f) ? packf(e) : 0u;
    }
}

// ======================= init: h0/c0 + Hp slab 0 =======================
__global__ void __launch_bounds__(256) init_kernel(
    const float* __restrict__ eh, const float* __restrict__ W1, const float* __restrict__ b1,
    const float* __restrict__ W2, const float* __restrict__ b2) {
    __shared__ float As[64][17], B1s[64][17], B2s[64][17];
    int m0 = blockIdx.y * 64, j0 = blockIdx.x * 64;
    int tid = threadIdx.x, tm = tid >> 4, tj = tid & 15;
    float acc1[4][4] = {}, acc2[4][4] = {};
    for (int k0 = 0; k0 < LL; k0 += 16) {
        int r = tid >> 2, c = (tid & 3) * 4;
        float4 va = *(const float4*)&eh[(m0 + r) * LL + k0 + c];
        As[r][c] = va.x; As[r][c+1] = va.y; As[r][c+2] = va.z; As[r][c+3] = va.w;
        float4 v1 = *(const float4*)&W1[(j0 + r) * LL + k0 + c];
        B1s[r][c] = v1.x; B1s[r][c+1] = v1.y; B1s[r][c+2] = v1.z; B1s[r][c+3] = v1.w;
        float4 v2 = *(const float4*)&W2[(j0 + r) * LL + k0 + c];
        B2s[r][c] = v2.x; B2s[r][c+1] = v2.y; B2s[r][c+2] = v2.z; B2s[r][c+3] = v2.w;
        __syncthreads();
        #pragma unroll
        for (int kk = 0; kk < 16; kk++) {
            float a[4], u[4], v[4];
            #pragma unroll
            for (int i = 0; i < 4; i++) a[i] = As[tm * 4 + i][kk];
            #pragma unroll
            for (int jv = 0; jv < 4; jv++) { u[jv] = B1s[tj + jv * 16][kk]; v[jv] = B2s[tj + jv * 16][kk]; }
            #pragma unroll
            for (int i = 0; i < 4; i++)
                #pragma unroll
                for (int jv = 0; jv < 4; jv++) { acc1[i][jv] += a[i] * u[jv]; acc2[i][jv] += a[i] * v[jv]; }
        }
        __syncthreads();
    }
    #pragma unroll
    for (int i = 0; i < 4; i++)
        #pragma unroll
        for (int jv = 0; jv < 4; jv++) {
            int m = m0 + tm * 4 + i, j = j0 + tj + jv * 16;
            float h0 = acc1[i][jv] + b1[j]; h0 = h0 > 0.f ? h0 : 0.01f * h0;
            float c0 = acc2[i][jv] + b2[j]; c0 = c0 > 0.f ? c0 : 0.01f * c0;
            size_t o = (size_t)m * HH + j;
            g_c[o] = c0;
            g_Hp[o] = packf(h0);                       // slab 0
        }
}

// ======================= y projection: MMA, packed A, pre-split Wout (round-6 proven) =======================
__device__ __forceinline__ void y_issue_B(uint32_t sb, int tid, int k0) {
    int r = tid >> 2, cc = tid & 3;
    uint32_t so = (uint32_t)r * 80 + (uint32_t)cc * 16;
    size_t gb = (size_t)r * HH + k0 + cc * 8;
    cp16(sb + 20480 + so, g_Wo_hi + gb);
    cp16(sb + 30720 + so, g_Wo_lo + gb);
}
__device__ __forceinline__ void y_load_A(const uint32_t* __restrict__ hp,
                                         int m0, int k0, int tid, ARegs32& R) {
    #pragma unroll
    for (int i = 0; i < 2; i++) {
        int idx = tid + i * 512, r = idx >> 3, cg = idx & 7;
        R.v[i] = *(const uint4*)(hp + (size_t)(m0 + r) * HH + k0 + cg * 4);
    }
}

__global__ void __launch_bounds__(512, 1) y_mma(const float* __restrict__ b_out,
                                                float* __restrict__ out_dec) {
    extern __shared__ char sm[];
    uint32_t sbase = smem_u32(sm);
    int tid = threadIdx.x, lane = tid & 31, wid = tid >> 5;
    int wm = wid & 3, wn = wid >> 2;
    int t = blockIdx.y, m0 = blockIdx.x * 128;
    const uint32_t* __restrict__ hp = g_Hp + (size_t)(t + 1) * BBHH;

    float acc[2][4][4];
    #pragma unroll
    for (int i = 0; i < 2; i++)
        #pragma unroll
        for (int nt = 0; nt < 4; nt++)
            #pragma unroll
            for (int q = 0; q < 4; q++) acc[i][nt][q] = 0.f;

    y_issue_B(sbase, tid, 0);  CP_COMMIT();
    y_issue_B(sbase + 40960u, tid, 32); CP_COMMIT();
    ARegs32 R;
    y_load_A(hp, m0, 0, tid, R);

    #pragma unroll 1
    for (int c = 0; c < 16; c++) {
        store_A32(sm + (c % 3) * 40960, tid, R);
        if (c == 15) { CP_WAIT0(); } else { CP_WAIT1(); }
        __syncthreads();
        if (c + 2 < 16) { y_issue_B(sbase + (uint32_t)((c + 2) % 3) * 40960u, tid, (c + 2) * 32); CP_COMMIT(); }
        if (c + 1 < 16) y_load_A(hp, m0, (c + 1) * 32, tid, R);
        tile_compute(sbase + (uint32_t)(c % 3) * 40960u, wm, wn, lane, acc);
    }

    #pragma unroll
    for (int i = 0; i < 2; i++)
        #pragma unroll
        for (int nt = 0; nt < 4; nt++)
            #pragma unroll
            for (int q = 0; q < 4; q++) {
                int m = m0 + wm * 32 + i * 16 + (lane >> 2) + (q >> 1) * 8;
                int o = wn * 32 + nt * 8 + (lane & 3) * 2 + (q & 1);
                out_dec[((size_t)m * SEQ + t) * OO + o] = acc[i][nt][q] + b_out[o];
            }
}

__global__ void hc_kernel(float* __restrict__ out_h, float* __restrict__ out_c) {
    int i = blockIdx.x * blockDim.x + threadIdx.x;
    if (i < BBHH) {
        out_h[i] = unpackf(g_Hp[(size_t)SEQ * BBHH + i]);
        out_c[i] = g_c[i];
    }
}

// ======================= num head: MMA pipeline + fused 2nd layer (round-6 proven) =======================
__device__ __forceinline__ void num_issue(uint32_t sbase, int stage, int tid, int m0, int chunk) {
    int nq = chunk >> 3, k0 = (chunk & 7) * 32;
    uint32_t sb = sbase + (uint32_t)stage * 40960u;
    int r = tid >> 2, cc = tid & 3;
    uint32_t so = (uint32_t)r * 80 + (uint32_t)cc * 16;
    size_t ga = (size_t)(m0 + r) * LL + k0 + cc * 8;
    size_t gb = (size_t)(nq * 128 + r) * LL + k0 + cc * 8;
    cp16(sb + so,         g_Eh + ga);
    cp16(sb + 10240 + so, g_El + ga);
    cp16(sb + 20480 + so, g_Ws_hi + gb);
    cp16(sb + 30720 + so, g_Ws_lo + gb);
}

#define NUM_SMEM (122880 + 2048)

__global__ void __launch_bounds__(512, 1) num_mma(
    const float* __restrict__ bseq, const float* __restrict__ w2,
    const float* __restrict__ b2, float* __restrict__ outnum) {
    extern __shared__ char sm[];
    uint32_t sbase = smem_u32(sm);
    int tid = threadIdx.x, lane = tid & 31, wid = tid >> 5;
    int wm = wid & 3, wn = wid >> 2;
    int m0 = blockIdx.x * 128;

    float acc[2][4][4];
    #pragma unroll
    for (int i = 0; i < 2; i++)
        #pragma unroll
        for (int nt = 0; nt < 4; nt++)
            #pragma unroll
            for (int q = 0; q < 4; q++) acc[i][nt][q] = 0.f;
    float s[4] = {0.f, 0.f, 0.f, 0.f};

    num_issue(sbase, 0, tid, m0, 0); CP_COMMIT();
    num_issue(sbase, 1, tid, m0, 1); CP_COMMIT();
    #pragma unroll 1
    for (int c = 0; c < 32; c++) {
        if (c == 31) { CP_WAIT0(); } else { CP_WAIT1(); }
        __syncthreads();
        if (c + 2 < 32) { num_issue(sbase, (c + 2) % 3, tid, m0, c + 2); CP_COMMIT(); }
        tile_compute(sbase + (uint32_t)(c % 3) * 40960u, wm, wn, lane, acc);
        if ((c & 7) == 7) {
            int nq = c >> 3;
            #pragma unroll
            for (int i = 0; i < 2; i++)
                #pragma unroll
                for (int nt = 0; nt < 4; nt++)
                    #pragma unroll
                    for (int q = 0; q < 4; q++) {
                        int rh = q >> 1, cc2 = q & 1;
                        int j = nq * 128 + wn * 32 + nt * 8 + (lane & 3) * 2 + cc2;
                        float v = acc[i][nt][q] + __ldg(&bseq[j]);
                        v = v > 0.f ? v : 0.01f * v;
                        s[i * 2 + rh] += v * __ldg(&w2[j]);
                        acc[i][nt][q] = 0.f;
                    }
        }
    }
    #pragma unroll
    for (int q = 0; q < 4; q++) {
        s[q] += __shfl_xor_sync(0xFFFFFFFFu, s[q], 1);
        s[q] += __shfl_xor_sync(0xFFFFFFFFu, s[q], 2);
    }
    float* P = (float*)(sm + 122880);
    if ((lane & 3) == 0) {
        #pragma unroll
        for (int i = 0; i < 2; i++)
            #pragma unroll
            for (int rh = 0; rh < 2; rh++) {
                int ml = wm * 32 + i * 16 + rh * 8 + (lane >> 2);
                P[wn * 128 + ml] = s[i * 2 + rh];
            }
    }
    __syncthreads();
    if (tid < 128) {
        float v = P[tid] + P[128 + tid] + P[256 + tid] + P[384 + tid] + b2[0];
        outnum[m0 + tid] = v > 0.f ? v : 0.f;
    }
}

// ======================= launch =======================
extern "C" void kernel_launch(void* const* d_in, const int* in_sizes, int n_in,
                              void* d_out, int out_size) {
    const float* enc_out = (const float*)d_in[0];
    const float* enc_hid = (const float*)d_in[1];
    const float* start   = (const float*)d_in[2];
    const float* W1   = (const float*)d_in[3];
    const float* b1   = (const float*)d_in[4];
    const float* W2   = (const float*)d_in[5];
    const float* b2   = (const float*)d_in[6];
    const float* Wemb = (const float*)d_in[7];
    const float* bemb = (const float*)d_in[8];
    const float* Wih  = (const float*)d_in[9];
    const float* Whh  = (const float*)d_in[10];
    const float* bih  = (const float*)d_in[11];
    const float* bhh  = (const float*)d_in[12];
    const float* Wout = (const float*)d_in[13];
    const float* bout = (const float*)d_in[14];
    const float* Wseq = (const float*)d_in[15];
    const float* bseq = (const float*)d_in[16];
    const float* Wsq2 = (const float*)d_in[17];
    const float* bsq2 = (const float*)d_in[18];
    // d_in[19] = seq_len (constant 100; hardcoded)

    float* out = (float*)d_out;
    float* out_dec = out;                           // [B, SEQ, O]
    float* out_h   = out + (size_t)BB * SEQ * OO;   // [1, B, H]
    float* out_c   = out_h + (size_t)BBHH;          // [1, B, H]
    float* out_num = out_c + (size_t)BBHH;          // [B, TENC, 1]

    cudaFuncSetAttribute(step_persist, cudaFuncAttributeMaxDynamicSharedMemorySize, S2_SMEM);
    cudaFuncSetAttribute(y_mma, cudaFuncAttributeMaxDynamicSharedMemorySize, 122880);
    cudaFuncSetAttribute(num_mma, cudaFuncAttributeMaxDynamicSharedMemorySize, NUM_SMEM);

    prep_w<<<(H4 * K2H + 255) / 256, 256>>>(Wih, Whh, bih, bhh, start, Wemb, bemb);
    prep2E<<<(int)(((size_t)BTENC * LL / 4 + 255) / 256), 256>>>(enc_out);
    prep2W<<<(HH * LL + 255) / 256, 256>>>(Wseq, Wout);
    init_kernel<<<dim3(HH / 64, BB / 64), 256>>>(enc_hid, W1, b1, W2, b2);
    seed_ax<<<(BBHH + 255) / 256, 256>>>();

    step_persist<<<dim3(16, 16), 256, S2_SMEM>>>();

    y_mma<<<dim3(BB / 128, SEQ), 512, 122880>>>(bout, out_dec);
    hc_kernel<<<(BBHH + 255) / 256, 256>>>(out_h, out_c);
    num_mma<<<BTENC / 128, 512, NUM_SMEM>>>(bseq, Wsq2, bsq2, out_num);
}

// round 14
// speedup vs baseline: 1.2758x; 1.0785x over previous
#include <cuda_runtime.h>
#include <cuda_bf16.h>
#include <math.h>
#include <stdint.h>

// Problem constants (fixed by setup_inputs)
#define BB   1024
#define LL   256
#define HH   512
#define OO   128
#define TENC 200
#define SEQ  100
#define H4   2048
#define K2H  1024
#define BTENC (BB*TENC)
#define BBHH (BB*HH)
#define NCTAS 256
#define NUMCTAS 40
#define TILES_PER_NUMCTA 80   // 3200 M64 tiles / 40 CTAs

// ======================= helpers =======================
__device__ __forceinline__ uint32_t smem_u32(const void* p) {
    uint32_t a;
    asm("{ .reg .u64 t; cvta.to.shared.u64 t, %1; cvt.u32.u64 %0, t; }" : "=r"(a) : "l"(p));
    return a;
}
__device__ __forceinline__ void ldm_x4(uint32_t* r, uint32_t addr) {
    asm volatile("ldmatrix.sync.aligned.m8n8.x4.shared.b16 {%0,%1,%2,%3}, [%4];"
                 : "=r"(r[0]), "=r"(r[1]), "=r"(r[2]), "=r"(r[3]) : "r"(addr));
}
__device__ __forceinline__ void mma16816(float* d, const uint32_t* a, const uint32_t* b) {
    asm volatile("mma.sync.aligned.m16n8k16.row.col.f32.bf16.bf16.f32 "
                 "{%0,%1,%2,%3}, {%4,%5,%6,%7}, {%8,%9}, {%0,%1,%2,%3};"
                 : "+f"(d[0]), "+f"(d[1]), "+f"(d[2]), "+f"(d[3])
                 : "r"(a[0]), "r"(a[1]), "r"(a[2]), "r"(a[3]), "r"(b[0]), "r"(b[1]));
}
__device__ __forceinline__ void cp16(uint32_t s, const void* g) {
    asm volatile("cp.async.cg.shared.global [%0], [%1], 16;" :: "r"(s), "l"(g));
}
#define CP_COMMIT() asm volatile("cp.async.commit_group;" ::: "memory")
#define CP_WAIT0()  asm volatile("cp.async.wait_group 0;" ::: "memory")
#define CP_WAIT1()  asm volatile("cp.async.wait_group 1;" ::: "memory")

__device__ __forceinline__ uint4 ldcg4(const uint32_t* p) {
    uint4 r;
    asm volatile("ld.global.cg.v4.u32 {%0,%1,%2,%3}, [%4];"
                 : "=r"(r.x), "=r"(r.y), "=r"(r.z), "=r"(r.w) : "l"(p));
    return r;
}
__device__ __forceinline__ uint32_t packf(float h) {
    __nv_bfloat16 hh = __float2bfloat16(h);
    __nv_bfloat16 hl = __float2bfloat16(h - __bfloat162float(hh));
    return (uint32_t)__bfloat16_as_ushort(hh) | ((uint32_t)__bfloat16_as_ushort(hl) << 16);
}
__device__ __forceinline__ float unpackf(uint32_t p) {
    __nv_bfloat16 hi = __ushort_as_bfloat16((unsigned short)(p & 0xFFFFu));
    __nv_bfloat16 lo = __ushort_as_bfloat16((unsigned short)(p >> 16));
    return __bfloat162float(hi) + __bfloat162float(lo);
}
__device__ __forceinline__ float sigf(float x) { return 1.f / (1.f + __expf(-x)); }

// ======================= device scratch =======================
__device__ __align__(16) uint32_t g_Hp[(size_t)(SEQ + 1) * BBHH]; // packed h history; slab 0 = h0
__device__ __align__(16) uint32_t g_Ax[2][BBHH];                  // packed relu(x) side, dbl-buffered
__device__ __align__(16) float g_c[BBHH];
__device__ __align__(16) float g_emb[HH];
__device__ __align__(16) float g_bcat[H4];                        // gate-major [g*HH + j]
__device__ __align__(16) __nv_bfloat16 g_Wb_hi[(size_t)H4 * K2H]; // interleaved rows n'=j*4+g
__device__ __align__(16) __nv_bfloat16 g_Wb_lo[(size_t)H4 * K2H];
__device__ __align__(16) __nv_bfloat16 g_Ws_hi[HH * LL];          // Wseq split [j][k]
__device__ __align__(16) __nv_bfloat16 g_Ws_lo[HH * LL];
__device__ __align__(16) __nv_bfloat16 g_Wo_hi[OO * HH];          // Wout split [o][k]
__device__ __align__(16) __nv_bfloat16 g_Wo_lo[OO * HH];
__device__ __align__(16) __nv_bfloat16 g_Eh[(size_t)BTENC * LL];  // enc_out split
__device__ __align__(16) __nv_bfloat16 g_El[(size_t)BTENC * LL];
__device__ unsigned g_bar_cnt = 0;
__device__ unsigned g_bar_gen = 0;

// ======================= grid barrier (256 LSTM CTAs only) =======================
__device__ __forceinline__ void gridbar() {
    __syncthreads();
    if (threadIdx.x == 0) {
        __threadfence();
        volatile unsigned* vgen = (volatile unsigned*)&g_bar_gen;
        unsigned gen = *vgen;
        if (atomicAdd(&g_bar_cnt, 1u) == NCTAS - 1u) {
            g_bar_cnt = 0u;
            __threadfence();
            atomicAdd(&g_bar_gen, 1u);
        } else {
            while (*vgen == gen) { __nanosleep(64); }
        }
    }
    __syncthreads();
}

// ======================= 512-thread 32-k stage machinery (y_mma, round-6 proven) =======================
// stage layout: A_hi[128][80B] @0, A_lo @10240, B_hi @20480, B_lo @30720; stage = 40960 B.
__device__ __forceinline__ void tile_compute(uint32_t sa, int wm, int wn, int lane, float acc[2][4][4]) {
    #pragma unroll
    for (int kk = 0; kk < 32; kk += 16) {
        uint32_t ah[2][4], al[2][4], bh[2][4], bl[2][4];
        #pragma unroll
        for (int i = 0; i < 2; i++) {
            uint32_t ad = sa + (uint32_t)(wm * 32 + i * 16 + (lane & 15)) * 80
                        + (uint32_t)(kk + (lane >> 4) * 8) * 2;
            ldm_x4(ah[i], ad);
            ldm_x4(al[i], ad + 10240);
        }
        #pragma unroll
        for (int s = 0; s < 2; s++) {
            uint32_t bd = sa + 20480 + (uint32_t)(wn * 32 + s * 16 + (lane >> 4) * 8 + (lane & 7)) * 80
                        + (uint32_t)(kk + ((lane >> 3) & 1) * 8) * 2;
            ldm_x4(bh[s], bd);
            ldm_x4(bl[s], bd + 10240);
        }
        #pragma unroll
        for (int i = 0; i < 2; i++)
            #pragma unroll
            for (int nt = 0; nt < 4; nt++)
                mma16816(acc[i][nt], ah[i], &bh[nt >> 1][(nt & 1) * 2]);
        #pragma unroll
        for (int i = 0; i < 2; i++)
            #pragma unroll
            for (int nt = 0; nt < 4; nt++)
                mma16816(acc[i][nt], ah[i], &bl[nt >> 1][(nt & 1) * 2]);
        #pragma unroll
        for (int i = 0; i < 2; i++)
            #pragma unroll
            for (int nt = 0; nt < 4; nt++)
                mma16816(acc[i][nt], al[i], &bh[nt >> 1][(nt & 1) * 2]);
    }
}

struct ARegs32 { uint4 v[2]; };
__device__ __forceinline__ void store_A32(char* base, int tid, const ARegs32& R) {
    #pragma unroll
    for (int i = 0; i < 2; i++) {
        int idx = tid + i * 512, r = idx >> 3, cg = idx & 7;
        uint4 P = R.v[i];
        uint32_t h0 = __byte_perm(P.x, P.y, 0x5410);
        uint32_t h1 = __byte_perm(P.z, P.w, 0x5410);
        uint32_t l0 = __byte_perm(P.x, P.y, 0x7632);
        uint32_t l1 = __byte_perm(P.z, P.w, 0x7632);
        uint32_t off = (uint32_t)r * 80 + (uint32_t)cg * 8;
        *(uint2*)(base + off) = make_uint2(h0, h1);
        *(uint2*)(base + 10240 + off) = make_uint2(l0, l1);
    }
}

// ======================= M64/K64 2-stage machinery (step + num paths) =======================
// stage: A_hi[64][144B] @0 (9216), A_lo @9216, B_hi[128][144B] @18432 (18432), B_lo @36864; stage = 55296.
#define S2_ALO   9216
#define S2_BHI   18432
#define S2_BLOD  18432
#define S2_STAGE 55296
#define S2_SMEM  (2 * S2_STAGE)

__device__ __forceinline__ void tile_compute64(uint32_t sa, int wm, int wn, int lane, float acc[2][4][4]) {
    #pragma unroll
    for (int kk = 0; kk < 64; kk += 16) {
        uint32_t ah[2][4], al[2][4], bh[2][4], bl[2][4];
        #pragma unroll
        for (int i = 0; i < 2; i++) {
            uint32_t ad = sa + (uint32_t)(wm * 32 + i * 16 + (lane & 15)) * 144
                        + (uint32_t)(kk + (lane >> 4) * 8) * 2;
            ldm_x4(ah[i], ad);
            ldm_x4(al[i], ad + S2_ALO);
        }
        #pragma unroll
        for (int s = 0; s < 2; s++) {
            uint32_t bd = sa + S2_BHI + (uint32_t)(wn * 32 + s * 16 + (lane >> 4) * 8 + (lane & 7)) * 144
                        + (uint32_t)(kk + ((lane >> 3) & 1) * 8) * 2;
            ldm_x4(bh[s], bd);
            ldm_x4(bl[s], bd + S2_BLOD);
        }
        #pragma unroll
        for (int i = 0; i < 2; i++)
            #pragma unroll
            for (int nt = 0; nt < 4; nt++)
                mma16816(acc[i][nt], ah[i], &bh[nt >> 1][(nt & 1) * 2]);
        #pragma unroll
        for (int i = 0; i < 2; i++)
            #pragma unroll
            for (int nt = 0; nt < 4; nt++)
                mma16816(acc[i][nt], ah[i], &bl[nt >> 1][(nt & 1) * 2]);
        #pragma unroll
        for (int i = 0; i < 2; i++)
            #pragma unroll
            for (int nt = 0; nt < 4; nt++)
                mma16816(acc[i][nt], al[i], &bh[nt >> 1][(nt & 1) * 2]);
    }
}

// --- step loaders (round-11 proven) ---
__device__ __forceinline__ void loadstore_A64(char* base,
                                              const uint32_t* __restrict__ ax,
                                              const uint32_t* __restrict__ hp,
                                              int m0, int k0, int tid) {
    #pragma unroll
    for (int i = 0; i < 4; i++) {
        int idx = tid + i * 256, r = idx >> 4, cg = idx & 15;  // r<64, cg<16
        int gk = k0 + cg * 4;
        const uint32_t* src = (gk < HH) ? (ax + (size_t)(m0 + r) * HH + gk)
                                        : (hp + (size_t)(m0 + r) * HH + (gk - HH));
        uint4 P = ldcg4(src);
        uint32_t h0 = __byte_perm(P.x, P.y, 0x5410);
        uint32_t h1 = __byte_perm(P.z, P.w, 0x5410);
        uint32_t l0 = __byte_perm(P.x, P.y, 0x7632);
        uint32_t l1 = __byte_perm(P.z, P.w, 0x7632);
        uint32_t off = (uint32_t)r * 144 + (uint32_t)cg * 8;
        *(uint2*)(base + off) = make_uint2(h0, h1);
        *(uint2*)(base + S2_ALO + off) = make_uint2(l0, l1);
    }
}
__device__ __forceinline__ void issue_B64(uint32_t sb, int tid, int j0, int k0) {
    #pragma unroll
    for (int i = 0; i < 8; i++) {
        int idx = tid + i * 256;                 // [0,2048)
        int half = idx >> 10;
        int w = idx & 1023;
        int rr = w >> 3, cc = w & 7;
        uint32_t so = (uint32_t)rr * 144 + (uint32_t)cc * 16;
        const __nv_bfloat16* src = half ? g_Wb_lo : g_Wb_hi;
        cp16(sb + S2_BHI + (uint32_t)half * S2_BLOD + so,
             src + (size_t)(j0 * 4 + rr) * K2H + k0 + cc * 8);
    }
}

// --- num loaders: E and Ws pre-split, both via cp.async ---
__device__ __forceinline__ void numA_issue(uint32_t sb, int tid, int m0, int k0) {
    #pragma unroll
    for (int i = 0; i < 4; i++) {
        int idx = tid + i * 256;                 // [0,1024)
        int half = idx >> 9;
        int w = idx & 511;
        int rr = w >> 3, cc = w & 7;             // r<64
        uint32_t so = (uint32_t)rr * 144 + (uint32_t)cc * 16;
        const __nv_bfloat16* src = half ? g_El : g_Eh;
        cp16(sb + (uint32_t)half * S2_ALO + so,
             src + (size_t)(m0 + rr) * LL + k0 + cc * 8);
    }
}
__device__ __forceinline__ void numB_issue(uint32_t sb, int tid, int j0, int k0) {
    #pragma unroll
    for (int i = 0; i < 8; i++) {
        int idx = tid + i * 256;                 // [0,2048)
        int half = idx >> 10;
        int w = idx & 1023;
        int rr = w >> 3, cc = w & 7;             // r<128
        uint32_t so = (uint32_t)rr * 144 + (uint32_t)cc * 16;
        const __nv_bfloat16* src = half ? g_Ws_lo : g_Ws_hi;
        cp16(sb + S2_BHI + (uint32_t)half * S2_BLOD + so,
             src + (size_t)(j0 + rr) * LL + k0 + cc * 8);
    }
}

// ======================= persistent kernel: LSTM loop (CTAs 0..255) + num head (CTAs 256..295) =======================
__global__ void __launch_bounds__(256, 2) step_persist(
    const float* __restrict__ bseq, const float* __restrict__ w2,
    const float* __restrict__ b2, float* __restrict__ outnum) {
    extern __shared__ char sm[];
    uint32_t sbase = smem_u32(sm);
    int tid = threadIdx.x, lane = tid & 31, wid = tid >> 5;
    int wm = wid & 1, wn = wid >> 1;
    int bx = blockIdx.x;

    if (bx < NCTAS) {
        // ---------------- LSTM path (round-11/13 proven, unchanged math) ----------------
        int j0 = (bx & 15) * 32, m0 = (bx >> 4) * 64;
        bool odd = (lane & 1) != 0;

        #pragma unroll 1
        for (int t = 0; t < SEQ; t++) {
            const uint32_t* __restrict__ ax = g_Ax[t & 1];
            const uint32_t* __restrict__ hp = g_Hp + (size_t)t * BBHH;

            float acc[2][4][4];
            #pragma unroll
            for (int i = 0; i < 2; i++)
                #pragma unroll
                for (int nt = 0; nt < 4; nt++)
                    #pragma unroll
                    for (int q = 0; q < 4; q++) acc[i][nt][q] = 0.f;

            issue_B64(sbase, tid, j0, 0);  CP_COMMIT();
            loadstore_A64(sm, ax, hp, m0, 0, tid);

            #pragma unroll 1
            for (int c = 0; c < 16; c++) {
                CP_WAIT0();
                __syncthreads();
                if (c + 1 < 16) {
                    issue_B64(sbase + (uint32_t)((c + 1) & 1) * S2_STAGE, tid, j0, (c + 1) * 64);
                    CP_COMMIT();
                    loadstore_A64(sm + ((c + 1) & 1) * S2_STAGE, ax, hp, m0, (c + 1) * 64, tid);
                }
                tile_compute64(sbase + (uint32_t)(c & 1) * S2_STAGE, wm, wn, lane, acc);
            }

            uint32_t* __restrict__ hpn = g_Hp + (size_t)(t + 1) * BBHH;
            uint32_t* __restrict__ axn = g_Ax[(t + 1) & 1];
            #pragma unroll
            for (int i = 0; i < 2; i++)
                #pragma unroll
                for (int nt = 0; nt < 4; nt++) {
                    float s0 = __shfl_xor_sync(0xFFFFFFFFu, acc[i][nt][0], 1);
                    float s1 = __shfl_xor_sync(0xFFFFFFFFu, acc[i][nt][1], 1);
                    float s2 = __shfl_xor_sync(0xFFFFFFFFu, acc[i][nt][2], 1);
                    float s3 = __shfl_xor_sync(0xFFFFFFFFu, acc[i][nt][3], 1);
                    int j = j0 + wn * 8 + nt * 2 + ((lane & 3) >> 1);
                    int m = m0 + wm * 32 + i * 16 + (lane >> 2) + (odd ? 8 : 0);
                    float gi = odd ? s2 : acc[i][nt][0];
                    float gf = odd ? s3 : acc[i][nt][1];
                    float gg = odd ? acc[i][nt][2] : s0;
                    float go = odd ? acc[i][nt][3] : s1;
                    gi += g_bcat[j]; gf += g_bcat[HH + j]; gg += g_bcat[2 * HH + j]; go += g_bcat[3 * HH + j];
                    size_t o = (size_t)m * HH + j;
                    float cn = sigf(gf) * g_c[o] + sigf(gi) * tanhf(gg);
                    g_c[o] = cn;
                    float h = sigf(go) * tanhf(cn);
                    uint32_t p = packf(h);
                    hpn[o] = p;
                    axn[o] = (h > 0.f) ? p : 0u;
                }

            if (t + 1 < SEQ) gridbar();
        }
    } else {
        // ---------------- num head path (idle SMs): relu(lrelu(E@Ws^T + bseq)@w2 + b2) ----------------
        int cta = bx - NCTAS;   // 0..39
        #pragma unroll 1
        for (int tIdx = 0; tIdx < TILES_PER_NUMCTA; tIdx++) {
            int m0 = (cta * TILES_PER_NUMCTA + tIdx) * 64;
            float s[4] = {0.f, 0.f, 0.f, 0.f};
            #pragma unroll 1
            for (int q = 0; q < 4; q++) {
                int j0 = q * 128;
                float acc[2][4][4];
                #pragma unroll
                for (int i = 0; i < 2; i++)
                    #pragma unroll
                    for (int nt = 0; nt < 4; nt++)
                        #pragma unroll
                        for (int qq = 0; qq < 4; qq++) acc[i][nt][qq] = 0.f;

                numA_issue(sbase, tid, m0, 0);
                numB_issue(sbase, tid, j0, 0);
                CP_COMMIT();
                #pragma unroll 1
                for (int c = 0; c < 4; c++) {
                    CP_WAIT0();
                    __syncthreads();
                    if (c + 1 < 4) {
                        numA_issue(sbase + (uint32_t)((c + 1) & 1) * S2_STAGE, tid, m0, (c + 1) * 64);
                        numB_issue(sbase + (uint32_t)((c + 1) & 1) * S2_STAGE, tid, j0, (c + 1) * 64);
                        CP_COMMIT();
                    }
                    tile_compute64(sbase + (uint32_t)(c & 1) * S2_STAGE, wm, wn, lane, acc);
                }
                // fold lrelu(P + bseq) * w2 into per-row partials
                #pragma unroll
                for (int i = 0; i < 2; i++)
                    #pragma unroll
                    for (int nt = 0; nt < 4; nt++)
                        #pragma unroll
                        for (int qq = 0; qq < 4; qq++) {
                            int j = j0 + wn * 32 + nt * 8 + (lane & 3) * 2 + (qq & 1);
                            float v = acc[i][nt][qq] + __ldg(&bseq[j]);
                            v = v > 0.f ? v : 0.01f * v;
                            s[i * 2 + (qq >> 1)] += v * __ldg(&w2[j]);
                        }
                __syncthreads();   // all warps done with stages before next quarter's cp.async
            }
            // deterministic reduction: shfl over lane&3, then smem over wn
            #pragma unroll
            for (int k = 0; k < 4; k++) {
                s[k] += __shfl_xor_sync(0xFFFFFFFFu, s[k], 1);
                s[k] += __shfl_xor_sync(0xFFFFFFFFu, s[k], 2);
            }
            float* P = (float*)sm;   // 4*64 floats in stage-0 A area
            if ((lane & 3) == 0) {
                #pragma unroll
                for (int i = 0; i < 2; i++)
                    #pragma unroll
                    for (int rh = 0; rh < 2; rh++)
                        P[wn * 64 + wm * 32 + i * 16 + rh * 8 + (lane >> 2)] = s[i * 2 + rh];
            }
            __syncthreads();
            if (tid < 64) {
                float v = P[tid] + P[64 + tid] + P[128 + tid] + P[192 + tid] + __ldg(&b2[0]);
                outnum[m0 + tid] = v > 0.f ? v : 0.f;
            }
            __syncthreads();   // P read done before next tile overwrites stage 0
        }
    }
}

// ======================= prep kernels =======================
__global__ void prep_w(const float* __restrict__ Wih, const float* __restrict__ Whh,
                       const float* __restrict__ bih, const float* __restrict__ bhh,
                       const float* __restrict__ st, const float* __restrict__ Wemb,
                       const float* __restrict__ bemb) {
    int idx = blockIdx.x * blockDim.x + threadIdx.x;
    if (idx < H4 * K2H) {
        int rn = idx / K2H, k = idx % K2H;
        int j = rn >> 2, g = rn & 3;
        int src = g * HH + j;
        float v = (k < HH) ? Wih[src * HH + k] : Whh[src * HH + (k - HH)];
        __nv_bfloat16 h = __float2bfloat16(v);
        g_Wb_hi[idx] = h;
        g_Wb_lo[idx] = __float2bfloat16(v - __bfloat162float(h));
    }
    if (idx < H4) g_bcat[idx] = bih[idx] + bhh[idx];
    if (blockIdx.x < 64) {  // emb: one warp per j
        int wid = threadIdx.x >> 5, lane = threadIdx.x & 31;
        int j = blockIdx.x * 8 + wid;
        float4 a = ((const float4*)st)[lane];
        float4 w = *(const float4*)&Wemb[j * OO + lane * 4];
        float s = a.x * w.x + a.y * w.y + a.z * w.z + a.w * w.w;
        #pragma unroll
        for (int o = 16; o; o >>= 1) s += __shfl_xor_sync(0xFFFFFFFFu, s, o);
        if (lane == 0) g_emb[j] = bemb[j] + s;
    }
}
__global__ void prep2E(const float* __restrict__ E) {
    size_t i = (size_t)blockIdx.x * blockDim.x + threadIdx.x;
    if (i < (size_t)BTENC * LL / 4) {
        float4 v = ((const float4*)E)[i];
        __nv_bfloat16 hx = __float2bfloat16(v.x), hy = __float2bfloat16(v.y);
        __nv_bfloat16 hz = __float2bfloat16(v.z), hw = __float2bfloat16(v.w);
        __nv_bfloat16 lx = __float2bfloat16(v.x - __bfloat162float(hx));
        __nv_bfloat16 ly = __float2bfloat16(v.y - __bfloat162float(hy));
        __nv_bfloat16 lz = __float2bfloat16(v.z - __bfloat162float(hz));
        __nv_bfloat16 lw = __float2bfloat16(v.w - __bfloat162float(hw));
        uint32_t h0 = (uint32_t)__bfloat16_as_ushort(hx) | ((uint32_t)__bfloat16_as_ushort(hy) << 16);
        uint32_t h1 = (uint32_t)__bfloat16_as_ushort(hz) | ((uint32_t)__bfloat16_as_ushort(hw) << 16);
        uint32_t l0 = (uint32_t)__bfloat16_as_ushort(lx) | ((uint32_t)__bfloat16_as_ushort(ly) << 16);
        uint32_t l1 = (uint32_t)__bfloat16_as_ushort(lz) | ((uint32_t)__bfloat16_as_ushort(lw) << 16);
        ((uint2*)g_Eh)[i] = make_uint2(h0, h1);
        ((uint2*)g_El)[i] = make_uint2(l0, l1);
    }
}
__global__ void prep2W(const float* __restrict__ Wseq, const float* __restrict__ Wout) {
    int i = blockIdx.x * blockDim.x + threadIdx.x;
    if (i < HH * LL) {
        float v = Wseq[i];
        __nv_bfloat16 h = __float2bfloat16(v);
        g_Ws_hi[i] = h;
        g_Ws_lo[i] = __float2bfloat16(v - __bfloat162float(h));
    }
    if (i < OO * HH) {
        float v = Wout[i];
        __nv_bfloat16 h = __float2bfloat16(v);
        g_Wo_hi[i] = h;
        g_Wo_lo[i] = __float2bfloat16(v - __bfloat162float(h));
    }
}
__global__ void seed_ax() {
    int i = blockIdx.x * blockDim.x + threadIdx.x;
    if (i < BBHH) {
        float e = g_emb[i & (HH - 1)];
        g_Ax[0][i] = (e > 0.f) ? packf(e) : 0u;
    }
}

// ======================= init: h0/c0 + Hp slab 0 =======================
__global__ void __launch_bounds__(256) init_kernel(
    const float* __restrict__ eh, const float* __restrict__ W1, const float* __restrict__ b1,
    const float* __restrict__ W2, const float* __restrict__ b2) {
    __shared__ float As[64][17], B1s[64][17], B2s[64][17];
    int m0 = blockIdx.y * 64, j0 = blockIdx.x * 64;
    int tid = threadIdx.x, tm = tid >> 4, tj = tid & 15;
    float acc1[4][4] = {}, acc2[4][4] = {};
    for (int k0 = 0; k0 < LL; k0 += 16) {
        int r = tid >> 2, c = (tid & 3) * 4;
        float4 va = *(const float4*)&eh[(m0 + r) * LL + k0 + c];
        As[r][c] = va.x; As[r][c+1] = va.y; As[r][c+2] = va.z; As[r][c+3] = va.w;
        float4 v1 = *(const float4*)&W1[(j0 + r) * LL + k0 + c];
        B1s[r][c] = v1.x; B1s[r][c+1] = v1.y; B1s[r][c+2] = v1.z; B1s[r][c+3] = v1.w;
        float4 v2 = *(const float4*)&W2[(j0 + r) * LL + k0 + c];
        B2s[r][c] = v2.x; B2s[r][c+1] = v2.y; B2s[r][c+2] = v2.z; B2s[r][c+3] = v2.w;
        __syncthreads();
        #pragma unroll
        for (int kk = 0; kk < 16; kk++) {
            float a[4], u[4], v[4];
            #pragma unroll
            for (int i = 0; i < 4; i++) a[i] = As[tm * 4 + i][kk];
            #pragma unroll
            for (int jv = 0; jv < 4; jv++) { u[jv] = B1s[tj + jv * 16][kk]; v[jv] = B2s[tj + jv * 16][kk]; }
            #pragma unroll
            for (int i = 0; i < 4; i++)
                #pragma unroll
                for (int jv = 0; jv < 4; jv++) { acc1[i][jv] += a[i] * u[jv]; acc2[i][jv] += a[i] * v[jv]; }
        }
        __syncthreads();
    }
    #pragma unroll
    for (int i = 0; i < 4; i++)
        #pragma unroll
        for (int jv = 0; jv < 4; jv++) {
            int m = m0 + tm * 4 + i, j = j0 + tj + jv * 16;
            float h0 = acc1[i][jv] + b1[j]; h0 = h0 > 0.f ? h0 : 0.01f * h0;
            float c0 = acc2[i][jv] + b2[j]; c0 = c0 > 0.f ? c0 : 0.01f * c0;
            size_t o = (size_t)m * HH + j;
            g_c[o] = c0;
            g_Hp[o] = packf(h0);                       // slab 0
        }
}

// ======================= y projection: MMA, packed A, pre-split Wout (round-6 proven) =======================
__device__ __forceinline__ void y_issue_B(uint32_t sb, int tid, int k0) {
    int r = tid >> 2, cc = tid & 3;
    uint32_t so = (uint32_t)r * 80 + (uint32_t)cc * 16;
    size_t gb = (size_t)r * HH + k0 + cc * 8;
    cp16(sb + 20480 + so, g_Wo_hi + gb);
    cp16(sb + 30720 + so, g_Wo_lo + gb);
}
__device__ __forceinline__ void y_load_A(const uint32_t* __restrict__ hp,
                                         int m0, int k0, int tid, ARegs32& R) {
    #pragma unroll
    for (int i = 0; i < 2; i++) {
        int idx = tid + i * 512, r = idx >> 3, cg = idx & 7;
        R.v[i] = *(const uint4*)(hp + (size_t)(m0 + r) * HH + k0 + cg * 4);
    }
}

__global__ void __launch_bounds__(512, 1) y_mma(const float* __restrict__ b_out,
                                                float* __restrict__ out_dec) {
    extern __shared__ char sm[];
    uint32_t sbase = smem_u32(sm);
    int tid = threadIdx.x, lane = tid & 31, wid = tid >> 5;
    int wm = wid & 3, wn = wid >> 2;
    int t = blockIdx.y, m0 = blockIdx.x * 128;
    const uint32_t* __restrict__ hp = g_Hp + (size_t)(t + 1) * BBHH;

    float acc[2][4][4];
    #pragma unroll
    for (int i = 0; i < 2; i++)
        #pragma unroll
        for (int nt = 0; nt < 4; nt++)
            #pragma unroll
            for (int q = 0; q < 4; q++) acc[i][nt][q] = 0.f;

    y_issue_B(sbase, tid, 0);  CP_COMMIT();
    y_issue_B(sbase + 40960u, tid, 32); CP_COMMIT();
    ARegs32 R;
    y_load_A(hp, m0, 0, tid, R);

    #pragma unroll 1
    for (int c = 0; c < 16; c++) {
        store_A32(sm + (c % 3) * 40960, tid, R);
        if (c == 15) { CP_WAIT0(); } else { CP_WAIT1(); }
        __syncthreads();
        if (c + 2 < 16) { y_issue_B(sbase + (uint32_t)((c + 2) % 3) * 40960u, tid, (c + 2) * 32); CP_COMMIT(); }
        if (c + 1 < 16) y_load_A(hp, m0, (c + 1) * 32, tid, R);
        tile_compute(sbase + (uint32_t)(c % 3) * 40960u, wm, wn, lane, acc);
    }

    #pragma unroll
    for (int i = 0; i < 2; i++)
        #pragma unroll
        for (int nt = 0; nt < 4; nt++)
            #pragma unroll
            for (int q = 0; q < 4; q++) {
                int m = m0 + wm * 32 + i * 16 + (lane >> 2) + (q >> 1) * 8;
                int o = wn * 32 + nt * 8 + (lane & 3) * 2 + (q & 1);
                out_dec[((size_t)m * SEQ + t) * OO + o] = acc[i][nt][q] + b_out[o];
            }
}

__global__ void hc_kernel(float* __restrict__ out_h, float* __restrict__ out_c) {
    int i = blockIdx.x * blockDim.x + threadIdx.x;
    if (i < BBHH) {
        out_h[i] = unpackf(g_Hp[(size_t)SEQ * BBHH + i]);
        out_c[i] = g_c[i];
    }
}

// ======================= launch =======================
extern "C" void kernel_launch(void* const* d_in, const int* in_sizes, int n_in,
                              void* d_out, int out_size) {
    const float* enc_out = (const float*)d_in[0];
    const float* enc_hid = (const float*)d_in[1];
    const float* start   = (const float*)d_in[2];
    const float* W1   = (const float*)d_in[3];
    const float* b1   = (const float*)d_in[4];
    const float* W2   = (const float*)d_in[5];
    const float* b2   = (const float*)d_in[6];
    const float* Wemb = (const float*)d_in[7];
    const float* bemb = (const float*)d_in[8];
    const float* Wih  = (const float*)d_in[9];
    const float* Whh  = (const float*)d_in[10];
    const float* bih  = (const float*)d_in[11];
    const float* bhh  = (const float*)d_in[12];
    const float* Wout = (const float*)d_in[13];
    const float* bout = (const float*)d_in[14];
    const float* Wseq = (const float*)d_in[15];
    const float* bseq = (const float*)d_in[16];
    const float* Wsq2 = (const float*)d_in[17];
    const float* bsq2 = (const float*)d_in[18];
    // d_in[19] = seq_len (constant 100; hardcoded)

    float* out = (float*)d_out;
    float* out_dec = out;                           // [B, SEQ, O]
    float* out_h   = out + (size_t)BB * SEQ * OO;   // [1, B, H]
    float* out_c   = out_h + (size_t)BBHH;          // [1, B, H]
    float* out_num = out_c + (size_t)BBHH;          // [B, TENC, 1]

    cudaFuncSetAttribute(step_persist, cudaFuncAttributeMaxDynamicSharedMemorySize, S2_SMEM);
    cudaFuncSetAttribute(y_mma, cudaFuncAttributeMaxDynamicSharedMemorySize, 122880);

    prep_w<<<(H4 * K2H + 255) / 256, 256>>>(Wih, Whh, bih, bhh, start, Wemb, bemb);
    prep2E<<<(int)(((size_t)BTENC * LL / 4 + 255) / 256), 256>>>(enc_out);
    prep2W<<<(HH * LL + 255) / 256, 256>>>(Wseq, Wout);
    init_kernel<<<dim3(HH / 64, BB / 64), 256>>>(enc_hid, W1, b1, W2, b2);
    seed_ax<<<(BBHH + 255) / 256, 256>>>();

    step_persist<<<NCTAS + NUMCTAS, 256, S2_SMEM>>>(bseq, Wsq2, bsq2, out_num);

    y_mma<<<dim3(BB / 128, SEQ), 512, 122880>>>(bout, out_dec);
    hc_kernel<<<(BBHH + 255) / 256, 256>>>(out_h, out_c);
}

// round 15
// speedup vs baseline: 1.3157x; 1.0313x over previous
#include <cuda_runtime.h>
#include <cuda_bf16.h>
#include <math.h>
#include <stdint.h>

// Problem constants (fixed by setup_inputs)
#define BB   1024
#define LL   256
#define HH   512
#define OO   128
#define TENC 200
#define SEQ  100
#define H4   2048
#define K2H  1024
#define BTENC (BB*TENC)
#define BBHH (BB*HH)
#define NCTAS 256
#define NUMCTAS 40
#define TILES_PER_NUMCTA 80   // 3200 M64 num tiles / 40 CTAs
#define YTASKS (99 * 16)      // y tiles for t=0..98 (t=99 handled post-kernel)

// ======================= helpers =======================
__device__ __forceinline__ uint32_t smem_u32(const void* p) {
    uint32_t a;
    asm("{ .reg .u64 t; cvta.to.shared.u64 t, %1; cvt.u32.u64 %0, t; }" : "=r"(a) : "l"(p));
    return a;
}
__device__ __forceinline__ void ldm_x4(uint32_t* r, uint32_t addr) {
    asm volatile("ldmatrix.sync.aligned.m8n8.x4.shared.b16 {%0,%1,%2,%3}, [%4];"
                 : "=r"(r[0]), "=r"(r[1]), "=r"(r[2]), "=r"(r[3]) : "r"(addr));
}
__device__ __forceinline__ void mma16816(float* d, const uint32_t* a, const uint32_t* b) {
    asm volatile("mma.sync.aligned.m16n8k16.row.col.f32.bf16.bf16.f32 "
                 "{%0,%1,%2,%3}, {%4,%5,%6,%7}, {%8,%9}, {%0,%1,%2,%3};"
                 : "+f"(d[0]), "+f"(d[1]), "+f"(d[2]), "+f"(d[3])
                 : "r"(a[0]), "r"(a[1]), "r"(a[2]), "r"(a[3]), "r"(b[0]), "r"(b[1]));
}
__device__ __forceinline__ void cp16(uint32_t s, const void* g) {
    asm volatile("cp.async.cg.shared.global [%0], [%1], 16;" :: "r"(s), "l"(g));
}
#define CP_COMMIT() asm volatile("cp.async.commit_group;" ::: "memory")
#define CP_WAIT0()  asm volatile("cp.async.wait_group 0;" ::: "memory")
#define CP_WAIT1()  asm volatile("cp.async.wait_group 1;" ::: "memory")

__device__ __forceinline__ uint4 ldcg4(const uint32_t* p) {
    uint4 r;
    asm volatile("ld.global.cg.v4.u32 {%0,%1,%2,%3}, [%4];"
                 : "=r"(r.x), "=r"(r.y), "=r"(r.z), "=r"(r.w) : "l"(p));
    return r;
}
__device__ __forceinline__ void split4(float4 v, uint32_t& h0, uint32_t& h1, uint32_t& l0, uint32_t& l1) {
    __nv_bfloat16 hx = __float2bfloat16(v.x), hy = __float2bfloat16(v.y);
    __nv_bfloat16 hz = __float2bfloat16(v.z), hw = __float2bfloat16(v.w);
    __nv_bfloat16 lx = __float2bfloat16(v.x - __bfloat162float(hx));
    __nv_bfloat16 ly = __float2bfloat16(v.y - __bfloat162float(hy));
    __nv_bfloat16 lz = __float2bfloat16(v.z - __bfloat162float(hz));
    __nv_bfloat16 lw = __float2bfloat16(v.w - __bfloat162float(hw));
    h0 = (uint32_t)__bfloat16_as_ushort(hx) | ((uint32_t)__bfloat16_as_ushort(hy) << 16);
    h1 = (uint32_t)__bfloat16_as_ushort(hz) | ((uint32_t)__bfloat16_as_ushort(hw) << 16);
    l0 = (uint32_t)__bfloat16_as_ushort(lx) | ((uint32_t)__bfloat16_as_ushort(ly) << 16);
    l1 = (uint32_t)__bfloat16_as_ushort(lz) | ((uint32_t)__bfloat16_as_ushort(lw) << 16);
}
__device__ __forceinline__ uint32_t packf(float h) {
    __nv_bfloat16 hh = __float2bfloat16(h);
    __nv_bfloat16 hl = __float2bfloat16(h - __bfloat162float(hh));
    return (uint32_t)__bfloat16_as_ushort(hh) | ((uint32_t)__bfloat16_as_ushort(hl) << 16);
}
__device__ __forceinline__ float unpackf(uint32_t p) {
    __nv_bfloat16 hi = __ushort_as_bfloat16((unsigned short)(p & 0xFFFFu));
    __nv_bfloat16 lo = __ushort_as_bfloat16((unsigned short)(p >> 16));
    return __bfloat162float(hi) + __bfloat162float(lo);
}
__device__ __forceinline__ float sigf(float x) { return 1.f / (1.f + __expf(-x)); }

// ======================= device scratch =======================
__device__ __align__(16) uint32_t g_Hp[(size_t)(SEQ + 1) * BBHH]; // packed h history; slab 0 = h0
__device__ __align__(16) uint32_t g_Ax[2][BBHH];                  // packed relu(x) side, dbl-buffered
__device__ __align__(16) float g_c[BBHH];
__device__ __align__(16) float g_emb[HH];
__device__ __align__(16) float g_bcat[H4];                        // gate-major [g*HH + j]
__device__ __align__(16) __nv_bfloat16 g_Wb_hi[(size_t)H4 * K2H]; // interleaved rows n'=j*4+g
__device__ __align__(16) __nv_bfloat16 g_Wb_lo[(size_t)H4 * K2H];
__device__ __align__(16) __nv_bfloat16 g_Ws_hi[HH * LL];          // Wseq split [j][k]
__device__ __align__(16) __nv_bfloat16 g_Ws_lo[HH * LL];
__device__ __align__(16) __nv_bfloat16 g_Wo_hi[OO * HH];          // Wout split [o][k]
__device__ __align__(16) __nv_bfloat16 g_Wo_lo[OO * HH];
__device__ unsigned g_bar_cnt = 0;
__device__ unsigned g_bar_gen = 0;

// ======================= grid barrier (256 LSTM CTAs only) =======================
__device__ __forceinline__ void gridbar() {
    __syncthreads();
    if (threadIdx.x == 0) {
        __threadfence();
        volatile unsigned* vgen = (volatile unsigned*)&g_bar_gen;
        unsigned gen = *vgen;
        if (atomicAdd(&g_bar_cnt, 1u) == NCTAS - 1u) {
            g_bar_cnt = 0u;
            __threadfence();
            atomicAdd(&g_bar_gen, 1u);
        } else {
            while (*vgen == gen) { __nanosleep(64); }
        }
    }
    __syncthreads();
}

// ======================= 512-thread 32-k stage machinery (post-kernel y_mma t=99) =======================
__device__ __forceinline__ void tile_compute(uint32_t sa, int wm, int wn, int lane, float acc[2][4][4]) {
    #pragma unroll
    for (int kk = 0; kk < 32; kk += 16) {
        uint32_t ah[2][4], al[2][4], bh[2][4], bl[2][4];
        #pragma unroll
        for (int i = 0; i < 2; i++) {
            uint32_t ad = sa + (uint32_t)(wm * 32 + i * 16 + (lane & 15)) * 80
                        + (uint32_t)(kk + (lane >> 4) * 8) * 2;
            ldm_x4(ah[i], ad);
            ldm_x4(al[i], ad + 10240);
        }
        #pragma unroll
        for (int s = 0; s < 2; s++) {
            uint32_t bd = sa + 20480 + (uint32_t)(wn * 32 + s * 16 + (lane >> 4) * 8 + (lane & 7)) * 80
                        + (uint32_t)(kk + ((lane >> 3) & 1) * 8) * 2;
            ldm_x4(bh[s], bd);
            ldm_x4(bl[s], bd + 10240);
        }
        #pragma unroll
        for (int i = 0; i < 2; i++)
            #pragma unroll
            for (int nt = 0; nt < 4; nt++)
                mma16816(acc[i][nt], ah[i], &bh[nt >> 1][(nt & 1) * 2]);
        #pragma unroll
        for (int i = 0; i < 2; i++)
            #pragma unroll
            for (int nt = 0; nt < 4; nt++)
                mma16816(acc[i][nt], ah[i], &bl[nt >> 1][(nt & 1) * 2]);
        #pragma unroll
        for (int i = 0; i < 2; i++)
            #pragma unroll
            for (int nt = 0; nt < 4; nt++)
                mma16816(acc[i][nt], al[i], &bh[nt >> 1][(nt & 1) * 2]);
    }
}
struct ARegs32 { uint4 v[2]; };
__device__ __forceinline__ void store_A32(char* base, int tid, const ARegs32& R) {
    #pragma unroll
    for (int i = 0; i < 2; i++) {
        int idx = tid + i * 512, r = idx >> 3, cg = idx & 7;
        uint4 P = R.v[i];
        uint32_t h0 = __byte_perm(P.x, P.y, 0x5410);
        uint32_t h1 = __byte_perm(P.z, P.w, 0x5410);
        uint32_t l0 = __byte_perm(P.x, P.y, 0x7632);
        uint32_t l1 = __byte_perm(P.z, P.w, 0x7632);
        uint32_t off = (uint32_t)r * 80 + (uint32_t)cg * 8;
        *(uint2*)(base + off) = make_uint2(h0, h1);
        *(uint2*)(base + 10240 + off) = make_uint2(l0, l1);
    }
}

// ======================= M64/K64 2-stage machinery =======================
// stage: A_hi[64][144B] @0, A_lo @9216, B_hi[128][144B] @18432, B_lo @36864; stage = 55296.
#define S2_ALO   9216
#define S2_BHI   18432
#define S2_BLOD  18432
#define S2_STAGE 55296
#define S2_SMEM  (2 * S2_STAGE)

__device__ __forceinline__ void tile_compute64(uint32_t sa, int wm, int wn, int lane, float acc[2][4][4]) {
    #pragma unroll
    for (int kk = 0; kk < 64; kk += 16) {
        uint32_t ah[2][4], al[2][4], bh[2][4], bl[2][4];
        #pragma unroll
        for (int i = 0; i < 2; i++) {
            uint32_t ad = sa + (uint32_t)(wm * 32 + i * 16 + (lane & 15)) * 144
                        + (uint32_t)(kk + (lane >> 4) * 8) * 2;
            ldm_x4(ah[i], ad);
            ldm_x4(al[i], ad + S2_ALO);
        }
        #pragma unroll
        for (int s = 0; s < 2; s++) {
            uint32_t bd = sa + S2_BHI + (uint32_t)(wn * 32 + s * 16 + (lane >> 4) * 8 + (lane & 7)) * 144
                        + (uint32_t)(kk + ((lane >> 3) & 1) * 8) * 2;
            ldm_x4(bh[s], bd);
            ldm_x4(bl[s], bd + S2_BLOD);
        }
        #pragma unroll
        for (int i = 0; i < 2; i++)
            #pragma unroll
            for (int nt = 0; nt < 4; nt++)
                mma16816(acc[i][nt], ah[i], &bh[nt >> 1][(nt & 1) * 2]);
        #pragma unroll
        for (int i = 0; i < 2; i++)
            #pragma unroll
            for (int nt = 0; nt < 4; nt++)
                mma16816(acc[i][nt], ah[i], &bl[nt >> 1][(nt & 1) * 2]);
        #pragma unroll
        for (int i = 0; i < 2; i++)
            #pragma unroll
            for (int nt = 0; nt < 4; nt++)
                mma16816(acc[i][nt], al[i], &bh[nt >> 1][(nt & 1) * 2]);
    }
}

// --- step loaders (round-11 proven) ---
__device__ __forceinline__ void loadstore_A64(char* base,
                                              const uint32_t* __restrict__ ax,
                                              const uint32_t* __restrict__ hp,
                                              int m0, int k0, int tid) {
    #pragma unroll
    for (int i = 0; i < 4; i++) {
        int idx = tid + i * 256, r = idx >> 4, cg = idx & 15;
        int gk = k0 + cg * 4;
        const uint32_t* src = (gk < HH) ? (ax + (size_t)(m0 + r) * HH + gk)
                                        : (hp + (size_t)(m0 + r) * HH + (gk - HH));
        uint4 P = ldcg4(src);
        uint32_t h0 = __byte_perm(P.x, P.y, 0x5410);
        uint32_t h1 = __byte_perm(P.z, P.w, 0x5410);
        uint32_t l0 = __byte_perm(P.x, P.y, 0x7632);
        uint32_t l1 = __byte_perm(P.z, P.w, 0x7632);
        uint32_t off = (uint32_t)r * 144 + (uint32_t)cg * 8;
        *(uint2*)(base + off) = make_uint2(h0, h1);
        *(uint2*)(base + S2_ALO + off) = make_uint2(l0, l1);
    }
}
__device__ __forceinline__ void issue_B64(uint32_t sb, int tid, int j0, int k0) {
    #pragma unroll
    for (int i = 0; i < 8; i++) {
        int idx = tid + i * 256;
        int half = idx >> 10;
        int w = idx & 1023;
        int rr = w >> 3, cc = w & 7;
        uint32_t so = (uint32_t)rr * 144 + (uint32_t)cc * 16;
        const __nv_bfloat16* src = half ? g_Wb_lo : g_Wb_hi;
        cp16(sb + S2_BHI + (uint32_t)half * S2_BLOD + so,
             src + (size_t)(j0 * 4 + rr) * K2H + k0 + cc * 8);
    }
}

// --- num loaders: A = fp32 E split in-kernel; B = pre-split Ws via cp.async ---
__device__ __forceinline__ void num_loadA(char* base, const float* __restrict__ E,
                                          int m0, int k0, int tid) {
    #pragma unroll
    for (int i = 0; i < 4; i++) {
        int idx = tid + i * 256, r = idx >> 4, cg = idx & 15;   // r<64
        float4 v = __ldg((const float4*)&E[(size_t)(m0 + r) * LL + k0 + cg * 4]);
        uint32_t h0, h1, l0, l1;
        split4(v, h0, h1, l0, l1);
        uint32_t off = (uint32_t)r * 144 + (uint32_t)cg * 8;
        *(uint2*)(base + off) = make_uint2(h0, h1);
        *(uint2*)(base + S2_ALO + off) = make_uint2(l0, l1);
    }
}
__device__ __forceinline__ void numB_issue(uint32_t sb, int tid, int j0, int k0) {
    #pragma unroll
    for (int i = 0; i < 8; i++) {
        int idx = tid + i * 256;
        int half = idx >> 10;
        int w = idx & 1023;
        int rr = w >> 3, cc = w & 7;
        uint32_t so = (uint32_t)rr * 144 + (uint32_t)cc * 16;
        const __nv_bfloat16* src = half ? g_Ws_lo : g_Ws_hi;
        cp16(sb + S2_BHI + (uint32_t)half * S2_BLOD + so,
             src + (size_t)(j0 + rr) * LL + k0 + cc * 8);
    }
}

// --- y loaders: A = packed h slab; B = pre-split Wout (128 rows x 512 k) ---
__device__ __forceinline__ void y_loadA(char* base, const uint32_t* __restrict__ hp,
                                        int m0, int k0, int tid) {
    #pragma unroll
    for (int i = 0; i < 4; i++) {
        int idx = tid + i * 256, r = idx >> 4, cg = idx & 15;   // r<64
        uint4 P = ldcg4(hp + (size_t)(m0 + r) * HH + k0 + cg * 4);
        uint32_t h0 = __byte_perm(P.x, P.y, 0x5410);
        uint32_t h1 = __byte_perm(P.z, P.w, 0x5410);
        uint32_t l0 = __byte_perm(P.x, P.y, 0x7632);
        uint32_t l1 = __byte_perm(P.z, P.w, 0x7632);
        uint32_t off = (uint32_t)r * 144 + (uint32_t)cg * 8;
        *(uint2*)(base + off) = make_uint2(h0, h1);
        *(uint2*)(base + S2_ALO + off) = make_uint2(l0, l1);
    }
}
__device__ __forceinline__ void yB_issue(uint32_t sb, int tid, int k0) {
    #pragma unroll
    for (int i = 0; i < 8; i++) {
        int idx = tid + i * 256;
        int half = idx >> 10;
        int w = idx & 1023;
        int rr = w >> 3, cc = w & 7;                // rr<128 (o rows)
        uint32_t so = (uint32_t)rr * 144 + (uint32_t)cc * 16;
        const __nv_bfloat16* src = half ? g_Wo_lo : g_Wo_hi;
        cp16(sb + S2_BHI + (uint32_t)half * S2_BLOD + so,
             src + (size_t)rr * HH + k0 + cc * 8);
    }
}

// ======================= persistent kernel =======================
__global__ void __launch_bounds__(256, 2) step_persist(
    const float* __restrict__ E, const float* __restrict__ bseq,
    const float* __restrict__ w2, const float* __restrict__ b2,
    float* __restrict__ outnum, const float* __restrict__ bout,
    float* __restrict__ out_dec) {
    extern __shared__ char sm[];
    uint32_t sbase = smem_u32(sm);
    int tid = threadIdx.x, lane = tid & 31, wid = tid >> 5;
    int wm = wid & 1, wn = wid >> 1;
    int bx = blockIdx.x;

    if (bx < NCTAS) {
        // ---------------- LSTM path (round-11/13/14 proven, unchanged) ----------------
        int j0 = (bx & 15) * 32, m0 = (bx >> 4) * 64;
        bool odd = (lane & 1) != 0;

        #pragma unroll 1
        for (int t = 0; t < SEQ; t++) {
            const uint32_t* __restrict__ ax = g_Ax[t & 1];
            const uint32_t* __restrict__ hp = g_Hp + (size_t)t * BBHH;

            float acc[2][4][4];
            #pragma unroll
            for (int i = 0; i < 2; i++)
                #pragma unroll
                for (int nt = 0; nt < 4; nt++)
                    #pragma unroll
                    for (int q = 0; q < 4; q++) acc[i][nt][q] = 0.f;

            issue_B64(sbase, tid, j0, 0);  CP_COMMIT();
            loadstore_A64(sm, ax, hp, m0, 0, tid);

            #pragma unroll 1
            for (int c = 0; c < 16; c++) {
                CP_WAIT0();
                __syncthreads();
                if (c + 1 < 16) {
                    issue_B64(sbase + (uint32_t)((c + 1) & 1) * S2_STAGE, tid, j0, (c + 1) * 64);
                    CP_COMMIT();
                    loadstore_A64(sm + ((c + 1) & 1) * S2_STAGE, ax, hp, m0, (c + 1) * 64, tid);
                }
                tile_compute64(sbase + (uint32_t)(c & 1) * S2_STAGE, wm, wn, lane, acc);
            }

            uint32_t* __restrict__ hpn = g_Hp + (size_t)(t + 1) * BBHH;
            uint32_t* __restrict__ axn = g_Ax[(t + 1) & 1];
            #pragma unroll
            for (int i = 0; i < 2; i++)
                #pragma unroll
                for (int nt = 0; nt < 4; nt++) {
                    float s0 = __shfl_xor_sync(0xFFFFFFFFu, acc[i][nt][0], 1);
                    float s1 = __shfl_xor_sync(0xFFFFFFFFu, acc[i][nt][1], 1);
                    float s2 = __shfl_xor_sync(0xFFFFFFFFu, acc[i][nt][2], 1);
                    float s3 = __shfl_xor_sync(0xFFFFFFFFu, acc[i][nt][3], 1);
                    int j = j0 + wn * 8 + nt * 2 + ((lane & 3) >> 1);
                    int m = m0 + wm * 32 + i * 16 + (lane >> 2) + (odd ? 8 : 0);
                    float gi = odd ? s2 : acc[i][nt][0];
                    float gf = odd ? s3 : acc[i][nt][1];
                    float gg = odd ? acc[i][nt][2] : s0;
                    float go = odd ? acc[i][nt][3] : s1;
                    gi += g_bcat[j]; gf += g_bcat[HH + j]; gg += g_bcat[2 * HH + j]; go += g_bcat[3 * HH + j];
                    size_t o = (size_t)m * HH + j;
                    float cn = sigf(gf) * g_c[o] + sigf(gi) * tanhf(gg);
                    g_c[o] = cn;
                    float h = sigf(go) * tanhf(cn);
                    uint32_t p = packf(h);
                    hpn[o] = p;
                    axn[o] = (h > 0.f) ? p : 0u;
                }

            if (t + 1 < SEQ) gridbar();
        }
    } else {
        int cta = bx - NCTAS;   // 0..39
        // ---------------- phase 1: num head ----------------
        #pragma unroll 1
        for (int tIdx = 0; tIdx < TILES_PER_NUMCTA; tIdx++) {
            int m0 = (cta * TILES_PER_NUMCTA + tIdx) * 64;
            float s[4] = {0.f, 0.f, 0.f, 0.f};
            #pragma unroll 1
            for (int q = 0; q < 4; q++) {
                int j0 = q * 128;
                float acc[2][4][4];
                #pragma unroll
                for (int i = 0; i < 2; i++)
                    #pragma unroll
                    for (int nt = 0; nt < 4; nt++)
                        #pragma unroll
                        for (int qq = 0; qq < 4; qq++) acc[i][nt][qq] = 0.f;

                numB_issue(sbase, tid, j0, 0); CP_COMMIT();
                num_loadA(sm, E, m0, 0, tid);
                #pragma unroll 1
                for (int c = 0; c < 4; c++) {
                    CP_WAIT0();
                    __syncthreads();
                    if (c + 1 < 4) {
                        numB_issue(sbase + (uint32_t)((c + 1) & 1) * S2_STAGE, tid, j0, (c + 1) * 64);
                        CP_COMMIT();
                        num_loadA(sm + ((c + 1) & 1) * S2_STAGE, E, m0, (c + 1) * 64, tid);
                    }
                    tile_compute64(sbase + (uint32_t)(c & 1) * S2_STAGE, wm, wn, lane, acc);
                }
                #pragma unroll
                for (int i = 0; i < 2; i++)
                    #pragma unroll
                    for (int nt = 0; nt < 4; nt++)
                        #pragma unroll
                        for (int qq = 0; qq < 4; qq++) {
                            int j = j0 + wn * 32 + nt * 8 + (lane & 3) * 2 + (qq & 1);
                            float v = acc[i][nt][qq] + __ldg(&bseq[j]);
                            v = v > 0.f ? v : 0.01f * v;
                            s[i * 2 + (qq >> 1)] += v * __ldg(&w2[j]);
                        }
                __syncthreads();
            }
            #pragma unroll
            for (int k = 0; k < 4; k++) {
                s[k] += __shfl_xor_sync(0xFFFFFFFFu, s[k], 1);
                s[k] += __shfl_xor_sync(0xFFFFFFFFu, s[k], 2);
            }
            float* P = (float*)sm;
            if ((lane & 3) == 0) {
                #pragma unroll
                for (int i = 0; i < 2; i++)
                    #pragma unroll
                    for (int rh = 0; rh < 2; rh++)
                        P[wn * 64 + wm * 32 + i * 16 + rh * 8 + (lane >> 2)] = s[i * 2 + rh];
            }
            __syncthreads();
            if (tid < 64) {
                float v = P[tid] + P[64 + tid] + P[128 + tid] + P[192 + tid] + __ldg(&b2[0]);
                outnum[m0 + tid] = v > 0.f ? v : 0.f;
            }
            __syncthreads();
        }
        // ---------------- phase 2: y projection for t=0..98, gated on barrier gen ----------------
        volatile unsigned* vgen = (volatile unsigned*)&g_bar_gen;
        #pragma unroll 1
        for (int task = cta; task < YTASKS; task += NUMCTAS) {
            int t = task >> 4, mt = task & 15;
            int m0 = mt * 64;
            if (tid == 0) {
                while (*vgen < (unsigned)(t + 1)) { __nanosleep(256); }
            }
            __syncthreads();
            const uint32_t* __restrict__ hp = g_Hp + (size_t)(t + 1) * BBHH;

            float acc[2][4][4];
            #pragma unroll
            for (int i = 0; i < 2; i++)
                #pragma unroll
                for (int nt = 0; nt < 4; nt++)
                    #pragma unroll
                    for (int q = 0; q < 4; q++) acc[i][nt][q] = 0.f;

            yB_issue(sbase, tid, 0); CP_COMMIT();
            y_loadA(sm, hp, m0, 0, tid);
            #pragma unroll 1
            for (int c = 0; c < 8; c++) {
                CP_WAIT0();
                __syncthreads();
                if (c + 1 < 8) {
                    yB_issue(sbase + (uint32_t)((c + 1) & 1) * S2_STAGE, tid, (c + 1) * 64);
                    CP_COMMIT();
                    y_loadA(sm + ((c + 1) & 1) * S2_STAGE, hp, m0, (c + 1) * 64, tid);
                }
                tile_compute64(sbase + (uint32_t)(c & 1) * S2_STAGE, wm, wn, lane, acc);
            }
            #pragma unroll
            for (int i = 0; i < 2; i++)
                #pragma unroll
                for (int nt = 0; nt < 4; nt++)
                    #pragma unroll
                    for (int q = 0; q < 4; q++) {
                        int o = wn * 32 + nt * 8 + (lane & 3) * 2 + (q & 1);
                        int m = m0 + wm * 32 + i * 16 + (lane >> 2) + (q >> 1) * 8;
                        out_dec[((size_t)m * SEQ + t) * OO + o] = acc[i][nt][q] + __ldg(&bout[o]);
                    }
            __syncthreads();
        }
    }
}

// ======================= prep kernels =======================
__global__ void prep_w(const float* __restrict__ Wih, const float* __restrict__ Whh,
                       const float* __restrict__ bih, const float* __restrict__ bhh,
                       const float* __restrict__ st, const float* __restrict__ Wemb,
                       const float* __restrict__ bemb) {
    int idx = blockIdx.x * blockDim.x + threadIdx.x;
    if (idx < H4 * K2H) {
        int rn = idx / K2H, k = idx % K2H;
        int j = rn >> 2, g = rn & 3;
        int src = g * HH + j;
        float v = (k < HH) ? Wih[src * HH + k] : Whh[src * HH + (k - HH)];
        __nv_bfloat16 h = __float2bfloat16(v);
        g_Wb_hi[idx] = h;
        g_Wb_lo[idx] = __float2bfloat16(v - __bfloat162float(h));
    }
    if (idx < H4) g_bcat[idx] = bih[idx] + bhh[idx];
    if (blockIdx.x < 64) {
        int wid = threadIdx.x >> 5, lane = threadIdx.x & 31;
        int j = blockIdx.x * 8 + wid;
        float4 a = ((const float4*)st)[lane];
        float4 w = *(const float4*)&Wemb[j * OO + lane * 4];
        float s = a.x * w.x + a.y * w.y + a.z * w.z + a.w * w.w;
        #pragma unroll
        for (int o = 16; o; o >>= 1) s += __shfl_xor_sync(0xFFFFFFFFu, s, o);
        if (lane == 0) g_emb[j] = bemb[j] + s;
    }
}
__global__ void prep2W(const float* __restrict__ Wseq, const float* __restrict__ Wout) {
    int i = blockIdx.x * blockDim.x + threadIdx.x;
    if (i < HH * LL) {
        float v = Wseq[i];
        __nv_bfloat16 h = __float2bfloat16(v);
        g_Ws_hi[i] = h;
        g_Ws_lo[i] = __float2bfloat16(v - __bfloat162float(h));
    }
    if (i < OO * HH) {
        float v = Wout[i];
        __nv_bfloat16 h = __float2bfloat16(v);
        g_Wo_hi[i] = h;
        g_Wo_lo[i] = __float2bfloat16(v - __bfloat162float(h));
    }
}
__global__ void seed_ax() {
    int i = blockIdx.x * blockDim.x + threadIdx.x;
    if (i < BBHH) {
        float e = g_emb[i & (HH - 1)];
        g_Ax[0][i] = (e > 0.f) ? packf(e) : 0u;
    }
}

// ======================= init: h0/c0 + Hp slab 0 =======================
__global__ void __launch_bounds__(256) init_kernel(
    const float* __restrict__ eh, const float* __restrict__ W1, const float* __restrict__ b1,
    const float* __restrict__ W2, const float* __restrict__ b2) {
    __shared__ float As[64][17], B1s[64][17], B2s[64][17];
    int m0 = blockIdx.y * 64, j0 = blockIdx.x * 64;
    int tid = threadIdx.x, tm = tid >> 4, tj = tid & 15;
    float acc1[4][4] = {}, acc2[4][4] = {};
    for (int k0 = 0; k0 < LL; k0 += 16) {
        int r = tid >> 2, c = (tid & 3) * 4;
        float4 va = *(const float4*)&eh[(m0 + r) * LL + k0 + c];
        As[r][c] = va.x; As[r][c+1] = va.y; As[r][c+2] = va.z; As[r][c+3] = va.w;
        float4 v1 = *(const float4*)&W1[(j0 + r) * LL + k0 + c];
        B1s[r][c] = v1.x; B1s[r][c+1] = v1.y; B1s[r][c+2] = v1.z; B1s[r][c+3] = v1.w;
        float4 v2 = *(const float4*)&W2[(j0 + r) * LL + k0 + c];
        B2s[r][c] = v2.x; B2s[r][c+1] = v2.y; B2s[r][c+2] = v2.z; B2s[r][c+3] = v2.w;
        __syncthreads();
        #pragma unroll
        for (int kk = 0; kk < 16; kk++) {
            float a[4], u[4], v[4];
            #pragma unroll
            for (int i = 0; i < 4; i++) a[i] = As[tm * 4 + i][kk];
            #pragma unroll
            for (int jv = 0; jv < 4; jv++) { u[jv] = B1s[tj + jv * 16][kk]; v[jv] = B2s[tj + jv * 16][kk]; }
            #pragma unroll
            for (int i = 0; i < 4; i++)
                #pragma unroll
                for (int jv = 0; jv < 4; jv++) { acc1[i][jv] += a[i] * u[jv]; acc2[i][jv] += a[i] * v[jv]; }
        }
        __syncthreads();
    }
    #pragma unroll
    for (int i = 0; i < 4; i++)
        #pragma unroll
        for (int jv = 0; jv < 4; jv++) {
            int m = m0 + tm * 4 + i, j = j0 + tj + jv * 16;
            float h0 = acc1[i][jv] + b1[j]; h0 = h0 > 0.f ? h0 : 0.01f * h0;
            float c0 = acc2[i][jv] + b2[j]; c0 = c0 > 0.f ? c0 : 0.01f * c0;
            size_t o = (size_t)m * HH + j;
            g_c[o] = c0;
            g_Hp[o] = packf(h0);
        }
}

// ======================= y_mma (t_base offset; used only for t=99 post-kernel) =======================
__device__ __forceinline__ void y_issue_B32(uint32_t sb, int tid, int k0) {
    int r = tid >> 2, cc = tid & 3;
    uint32_t so = (uint32_t)r * 80 + (uint32_t)cc * 16;
    size_t gb = (size_t)r * HH + k0 + cc * 8;
    cp16(sb + 20480 + so, g_Wo_hi + gb);
    cp16(sb + 30720 + so, g_Wo_lo + gb);
}
__device__ __forceinline__ void y_load_A32(const uint32_t* __restrict__ hp,
                                           int m0, int k0, int tid, ARegs32& R) {
    #pragma unroll
    for (int i = 0; i < 2; i++) {
        int idx = tid + i * 512, r = idx >> 3, cg = idx & 7;
        R.v[i] = *(const uint4*)(hp + (size_t)(m0 + r) * HH + k0 + cg * 4);
    }
}
__global__ void __launch_bounds__(512, 1) y_mma(const float* __restrict__ b_out,
                                                float* __restrict__ out_dec, int t_base) {
    extern __shared__ char sm[];
    uint32_t sbase = smem_u32(sm);
    int tid = threadIdx.x, lane = tid & 31, wid = tid >> 5;
    int wm = wid & 3, wn = wid >> 2;
    int t = blockIdx.y + t_base, m0 = blockIdx.x * 128;
    const uint32_t* __restrict__ hp = g_Hp + (size_t)(t + 1) * BBHH;

    float acc[2][4][4];
    #pragma unroll
    for (int i = 0; i < 2; i++)
        #pragma unroll
        for (int nt = 0; nt < 4; nt++)
            #pragma unroll
            for (int q = 0; q < 4; q++) acc[i][nt][q] = 0.f;

    y_issue_B32(sbase, tid, 0);  CP_COMMIT();
    y_issue_B32(sbase + 40960u, tid, 32); CP_COMMIT();
    ARegs32 R;
    y_load_A32(hp, m0, 0, tid, R);

    #pragma unroll 1
    for (int c = 0; c < 16; c++) {
        store_A32(sm + (c % 3) * 40960, tid, R);
        if (c == 15) { CP_WAIT0(); } else { CP_WAIT1(); }
        __syncthreads();
        if (c + 2 < 16) { y_issue_B32(sbase + (uint32_t)((c + 2) % 3) * 40960u, tid, (c + 2) * 32); CP_COMMIT(); }
        if (c + 1 < 16) y_load_A32(hp, m0, (c + 1) * 32, tid, R);
        tile_compute(sbase + (uint32_t)(c % 3) * 40960u, wm, wn, lane, acc);
    }

    #pragma unroll
    for (int i = 0; i < 2; i++)
        #pragma unroll
        for (int nt = 0; nt < 4; nt++)
            #pragma unroll
            for (int q = 0; q < 4; q++) {
                int m = m0 + wm * 32 + i * 16 + (lane >> 2) + (q >> 1) * 8;
                int o = wn * 32 + nt * 8 + (lane & 3) * 2 + (q & 1);
                out_dec[((size_t)m * SEQ + t) * OO + o] = acc[i][nt][q] + b_out[o];
            }
}

__global__ void hc_kernel(float* __restrict__ out_h, float* __restrict__ out_c) {
    int i = blockIdx.x * blockDim.x + threadIdx.x;
    if (i < BBHH) {
        out_h[i] = unpackf(g_Hp[(size_t)SEQ * BBHH + i]);
        out_c[i] = g_c[i];
    }
}

// ======================= launch =======================
extern "C" void kernel_launch(void* const* d_in, const int* in_sizes, int n_in,
                              void* d_out, int out_size) {
    const float* enc_out = (const float*)d_in[0];
    const float* enc_hid = (const float*)d_in[1];
    const float* start   = (const float*)d_in[2];
    const float* W1   = (const float*)d_in[3];
    const float* b1   = (const float*)d_in[4];
    const float* W2   = (const float*)d_in[5];
    const float* b2   = (const float*)d_in[6];
    const float* Wemb = (const float*)d_in[7];
    const float* bemb = (const float*)d_in[8];
    const float* Wih  = (const float*)d_in[9];
    const float* Whh  = (const float*)d_in[10];
    const float* bih  = (const float*)d_in[11];
    const float* bhh  = (const float*)d_in[12];
    const float* Wout = (const float*)d_in[13];
    const float* bout = (const float*)d_in[14];
    const float* Wseq = (const float*)d_in[15];
    const float* bseq = (const float*)d_in[16];
    const float* Wsq2 = (const float*)d_in[17];
    const float* bsq2 = (const float*)d_in[18];
    // d_in[19] = seq_len (constant 100; hardcoded)

    float* out = (float*)d_out;
    float* out_dec = out;                           // [B, SEQ, O]
    float* out_h   = out + (size_t)BB * SEQ * OO;   // [1, B, H]
    float* out_c   = out_h + (size_t)BBHH;          // [1, B, H]
    float* out_num = out_c + (size_t)BBHH;          // [B, TENC, 1]

    cudaFuncSetAttribute(step_persist, cudaFuncAttributeMaxDynamicSharedMemorySize, S2_SMEM);
    cudaFuncSetAttribute(y_mma, cudaFuncAttributeMaxDynamicSharedMemorySize, 122880);

    prep_w<<<(H4 * K2H + 255) / 256, 256>>>(Wih, Whh, bih, bhh, start, Wemb, bemb);
    prep2W<<<(HH * LL + 255) / 256, 256>>>(Wseq, Wout);
    init_kernel<<<dim3(HH / 64, BB / 64), 256>>>(enc_hid, W1, b1, W2, b2);
    seed_ax<<<(BBHH + 255) / 256, 256>>>();

    step_persist<<<NCTAS + NUMCTAS, 256, S2_SMEM>>>(enc_out, bseq, Wsq2, bsq2,
                                                     out_num, bout, out_dec);

    y_mma<<<dim3(BB / 128, 1), 512, 122880>>>(bout, out_dec, SEQ - 1);  // t=99 only
    hc_kernel<<<(BBHH + 255) / 256, 256>>>(out_h, out_c);
}

// round 16
// speedup vs baseline: 1.3625x; 1.0356x over previous
#include <cuda_runtime.h>
#include <cuda_bf16.h>
#include <math.h>
#include <stdint.h>

// Problem constants (fixed by setup_inputs)
#define BB   1024
#define LL   256
#define HH   512
#define OO   128
#define TENC 200
#define SEQ  100
#define H4   2048
#define K2H  1024
#define BTENC (BB*TENC)
#define BBHH (BB*HH)
#define NCTAS 256
#define NUMCTAS 40
#define TILES_PER_NUMCTA 80   // 3200 M64 num tiles / 40 CTAs
#define YTASKS (SEQ * 16)     // y tiles for t=0..99 (gen reaches 100)

// ======================= helpers =======================
__device__ __forceinline__ uint32_t smem_u32(const void* p) {
    uint32_t a;
    asm("{ .reg .u64 t; cvta.to.shared.u64 t, %1; cvt.u32.u64 %0, t; }" : "=r"(a) : "l"(p));
    return a;
}
__device__ __forceinline__ void ldm_x4(uint32_t* r, uint32_t addr) {
    asm volatile("ldmatrix.sync.aligned.m8n8.x4.shared.b16 {%0,%1,%2,%3}, [%4];"
                 : "=r"(r[0]), "=r"(r[1]), "=r"(r[2]), "=r"(r[3]) : "r"(addr));
}
__device__ __forceinline__ void mma16816(float* d, const uint32_t* a, const uint32_t* b) {
    asm volatile("mma.sync.aligned.m16n8k16.row.col.f32.bf16.bf16.f32 "
                 "{%0,%1,%2,%3}, {%4,%5,%6,%7}, {%8,%9}, {%0,%1,%2,%3};"
                 : "+f"(d[0]), "+f"(d[1]), "+f"(d[2]), "+f"(d[3])
                 : "r"(a[0]), "r"(a[1]), "r"(a[2]), "r"(a[3]), "r"(b[0]), "r"(b[1]));
}
__device__ __forceinline__ void cp16(uint32_t s, const void* g) {
    asm volatile("cp.async.cg.shared.global [%0], [%1], 16;" :: "r"(s), "l"(g));
}
#define CP_COMMIT() asm volatile("cp.async.commit_group;" ::: "memory")
#define CP_WAIT0()  asm volatile("cp.async.wait_group 0;" ::: "memory")

__device__ __forceinline__ uint4 ldcg4(const uint32_t* p) {
    uint4 r;
    asm volatile("ld.global.cg.v4.u32 {%0,%1,%2,%3}, [%4];"
                 : "=r"(r.x), "=r"(r.y), "=r"(r.z), "=r"(r.w) : "l"(p));
    return r;
}
__device__ __forceinline__ void split4(float4 v, uint32_t& h0, uint32_t& h1, uint32_t& l0, uint32_t& l1) {
    __nv_bfloat16 hx = __float2bfloat16(v.x), hy = __float2bfloat16(v.y);
    __nv_bfloat16 hz = __float2bfloat16(v.z), hw = __float2bfloat16(v.w);
    __nv_bfloat16 lx = __float2bfloat16(v.x - __bfloat162float(hx));
    __nv_bfloat16 ly = __float2bfloat16(v.y - __bfloat162float(hy));
    __nv_bfloat16 lz = __float2bfloat16(v.z - __bfloat162float(hz));
    __nv_bfloat16 lw = __float2bfloat16(v.w - __bfloat162float(hw));
    h0 = (uint32_t)__bfloat16_as_ushort(hx) | ((uint32_t)__bfloat16_as_ushort(hy) << 16);
    h1 = (uint32_t)__bfloat16_as_ushort(hz) | ((uint32_t)__bfloat16_as_ushort(hw) << 16);
    l0 = (uint32_t)__bfloat16_as_ushort(lx) | ((uint32_t)__bfloat16_as_ushort(ly) << 16);
    l1 = (uint32_t)__bfloat16_as_ushort(lz) | ((uint32_t)__bfloat16_as_ushort(lw) << 16);
}
__device__ __forceinline__ uint32_t packf(float h) {
    __nv_bfloat16 hh = __float2bfloat16(h);
    __nv_bfloat16 hl = __float2bfloat16(h - __bfloat162float(hh));
    return (uint32_t)__bfloat16_as_ushort(hh) | ((uint32_t)__bfloat16_as_ushort(hl) << 16);
}
__device__ __forceinline__ float unpackf(uint32_t p) {
    __nv_bfloat16 hi = __ushort_as_bfloat16((unsigned short)(p & 0xFFFFu));
    __nv_bfloat16 lo = __ushort_as_bfloat16((unsigned short)(p >> 16));
    return __bfloat162float(hi) + __bfloat162float(lo);
}
__device__ __forceinline__ float sigf(float x) { return 1.f / (1.f + __expf(-x)); }

// ======================= device scratch =======================
__device__ __align__(16) uint32_t g_Hp[(size_t)(SEQ + 1) * BBHH]; // packed h history; slab 0 = h0
__device__ __align__(16) uint32_t g_Ax[2][BBHH];                  // packed relu(x) side, dbl-buffered
__device__ __align__(16) float g_c[BBHH];
__device__ __align__(16) float g_emb[HH];
__device__ __align__(16) float g_bcat[H4];                        // gate-major [g*HH + j]
__device__ __align__(16) __nv_bfloat16 g_Wb_hi[(size_t)H4 * K2H]; // interleaved rows n'=j*4+g
__device__ __align__(16) __nv_bfloat16 g_Wb_lo[(size_t)H4 * K2H];
__device__ __align__(16) __nv_bfloat16 g_Ws_hi[HH * LL];          // Wseq split [j][k]
__device__ __align__(16) __nv_bfloat16 g_Ws_lo[HH * LL];
__device__ __align__(16) __nv_bfloat16 g_Wo_hi[OO * HH];          // Wout split [o][k]
__device__ __align__(16) __nv_bfloat16 g_Wo_lo[OO * HH];
__device__ unsigned g_gcnt[16 * 32];   // per-m-group barrier counters, 128B-strided
__device__ unsigned g_ggen[16 * 32];   // per-m-group generation

// ======================= per-m-group barrier (16 CTAs each) =======================
__device__ __forceinline__ void gridbar_grp(int grp) {
    __syncthreads();
    if (threadIdx.x == 0) {
        __threadfence();
        volatile unsigned* vgen = (volatile unsigned*)&g_ggen[grp * 32];
        unsigned gen = *vgen;
        if (atomicAdd(&g_gcnt[grp * 32], 1u) == 15u) {
            g_gcnt[grp * 32] = 0u;
            __threadfence();
            atomicAdd(&g_ggen[grp * 32], 1u);
        } else {
            while (*vgen == gen) { __nanosleep(32); }
        }
    }
    __syncthreads();
}

// ======================= M64/K64 2-stage machinery =======================
// stage: A_hi[64][144B] @0, A_lo @9216, B_hi[128][144B] @18432, B_lo @36864; stage = 55296.
#define S2_ALO   9216
#define S2_BHI   18432
#define S2_BLOD  18432
#define S2_STAGE 55296
#define S2_SMEM  (2 * S2_STAGE)

__device__ __forceinline__ void tile_compute64(uint32_t sa, int wm, int wn, int lane, float acc[2][4][4]) {
    #pragma unroll
    for (int kk = 0; kk < 64; kk += 16) {
        uint32_t ah[2][4], al[2][4], bh[2][4], bl[2][4];
        #pragma unroll
        for (int i = 0; i < 2; i++) {
            uint32_t ad = sa + (uint32_t)(wm * 32 + i * 16 + (lane & 15)) * 144
                        + (uint32_t)(kk + (lane >> 4) * 8) * 2;
            ldm_x4(ah[i], ad);
            ldm_x4(al[i], ad + S2_ALO);
        }
        #pragma unroll
        for (int s = 0; s < 2; s++) {
            uint32_t bd = sa + S2_BHI + (uint32_t)(wn * 32 + s * 16 + (lane >> 4) * 8 + (lane & 7)) * 144
                        + (uint32_t)(kk + ((lane >> 3) & 1) * 8) * 2;
            ldm_x4(bh[s], bd);
            ldm_x4(bl[s], bd + S2_BLOD);
        }
        #pragma unroll
        for (int i = 0; i < 2; i++)
            #pragma unroll
            for (int nt = 0; nt < 4; nt++)
                mma16816(acc[i][nt], ah[i], &bh[nt >> 1][(nt & 1) * 2]);
        #pragma unroll
        for (int i = 0; i < 2; i++)
            #pragma unroll
            for (int nt = 0; nt < 4; nt++)
                mma16816(acc[i][nt], ah[i], &bl[nt >> 1][(nt & 1) * 2]);
        #pragma unroll
        for (int i = 0; i < 2; i++)
            #pragma unroll
            for (int nt = 0; nt < 4; nt++)
                mma16816(acc[i][nt], al[i], &bh[nt >> 1][(nt & 1) * 2]);
    }
}

// --- step loaders (round-11 proven) ---
__device__ __forceinline__ void loadstore_A64(char* base,
                                              const uint32_t* __restrict__ ax,
                                              const uint32_t* __restrict__ hp,
                                              int m0, int k0, int tid) {
    #pragma unroll
    for (int i = 0; i < 4; i++) {
        int idx = tid + i * 256, r = idx >> 4, cg = idx & 15;
        int gk = k0 + cg * 4;
        const uint32_t* src = (gk < HH) ? (ax + (size_t)(m0 + r) * HH + gk)
                                        : (hp + (size_t)(m0 + r) * HH + (gk - HH));
        uint4 P = ldcg4(src);
        uint32_t h0 = __byte_perm(P.x, P.y, 0x5410);
        uint32_t h1 = __byte_perm(P.z, P.w, 0x5410);
        uint32_t l0 = __byte_perm(P.x, P.y, 0x7632);
        uint32_t l1 = __byte_perm(P.z, P.w, 0x7632);
        uint32_t off = (uint32_t)r * 144 + (uint32_t)cg * 8;
        *(uint2*)(base + off) = make_uint2(h0, h1);
        *(uint2*)(base + S2_ALO + off) = make_uint2(l0, l1);
    }
}
__device__ __forceinline__ void issue_B64(uint32_t sb, int tid, int j0, int k0) {
    #pragma unroll
    for (int i = 0; i < 8; i++) {
        int idx = tid + i * 256;
        int half = idx >> 10;
        int w = idx & 1023;
        int rr = w >> 3, cc = w & 7;
        uint32_t so = (uint32_t)rr * 144 + (uint32_t)cc * 16;
        const __nv_bfloat16* src = half ? g_Wb_lo : g_Wb_hi;
        cp16(sb + S2_BHI + (uint32_t)half * S2_BLOD + so,
             src + (size_t)(j0 * 4 + rr) * K2H + k0 + cc * 8);
    }
}

// --- num loaders: A = fp32 E split in-kernel; B = pre-split Ws via cp.async ---
__device__ __forceinline__ void num_loadA(char* base, const float* __restrict__ E,
                                          int m0, int k0, int tid) {
    #pragma unroll
    for (int i = 0; i < 4; i++) {
        int idx = tid + i * 256, r = idx >> 4, cg = idx & 15;
        float4 v = __ldg((const float4*)&E[(size_t)(m0 + r) * LL + k0 + cg * 4]);
        uint32_t h0, h1, l0, l1;
        split4(v, h0, h1, l0, l1);
        uint32_t off = (uint32_t)r * 144 + (uint32_t)cg * 8;
        *(uint2*)(base + off) = make_uint2(h0, h1);
        *(uint2*)(base + S2_ALO + off) = make_uint2(l0, l1);
    }
}
__device__ __forceinline__ void numB_issue(uint32_t sb, int tid, int j0, int k0) {
    #pragma unroll
    for (int i = 0; i < 8; i++) {
        int idx = tid + i * 256;
        int half = idx >> 10;
        int w = idx & 1023;
        int rr = w >> 3, cc = w & 7;
        uint32_t so = (uint32_t)rr * 144 + (uint32_t)cc * 16;
        const __nv_bfloat16* src = half ? g_Ws_lo : g_Ws_hi;
        cp16(sb + S2_BHI + (uint32_t)half * S2_BLOD + so,
             src + (size_t)(j0 + rr) * LL + k0 + cc * 8);
    }
}

// --- y loaders: A = packed h slab; B = pre-split Wout ---
__device__ __forceinline__ void y_loadA(char* base, const uint32_t* __restrict__ hp,
                                        int m0, int k0, int tid) {
    #pragma unroll
    for (int i = 0; i < 4; i++) {
        int idx = tid + i * 256, r = idx >> 4, cg = idx & 15;
        uint4 P = ldcg4(hp + (size_t)(m0 + r) * HH + k0 + cg * 4);
        uint32_t h0 = __byte_perm(P.x, P.y, 0x5410);
        uint32_t h1 = __byte_perm(P.z, P.w, 0x5410);
        uint32_t l0 = __byte_perm(P.x, P.y, 0x7632);
        uint32_t l1 = __byte_perm(P.z, P.w, 0x7632);
        uint32_t off = (uint32_t)r * 144 + (uint32_t)cg * 8;
        *(uint2*)(base + off) = make_uint2(h0, h1);
        *(uint2*)(base + S2_ALO + off) = make_uint2(l0, l1);
    }
}
__device__ __forceinline__ void yB_issue(uint32_t sb, int tid, int k0) {
    #pragma unroll
    for (int i = 0; i < 8; i++) {
        int idx = tid + i * 256;
        int half = idx >> 10;
        int w = idx & 1023;
        int rr = w >> 3, cc = w & 7;
        uint32_t so = (uint32_t)rr * 144 + (uint32_t)cc * 16;
        const __nv_bfloat16* src = half ? g_Wo_lo : g_Wo_hi;
        cp16(sb + S2_BHI + (uint32_t)half * S2_BLOD + so,
             src + (size_t)rr * HH + k0 + cc * 8);
    }
}

// ======================= persistent kernel =======================
__global__ void __launch_bounds__(256, 2) step_persist(
    const float* __restrict__ E, const float* __restrict__ bseq,
    const float* __restrict__ w2, const float* __restrict__ b2,
    float* __restrict__ outnum, const float* __restrict__ bout,
    float* __restrict__ out_dec) {
    extern __shared__ char sm[];
    uint32_t sbase = smem_u32(sm);
    int tid = threadIdx.x, lane = tid & 31, wid = tid >> 5;
    int wm = wid & 1, wn = wid >> 1;
    int bx = blockIdx.x;

    if (bx < NCTAS) {
        // ---------------- LSTM path; barrier is per-m-group (16 CTAs), every step ----------------
        int j0 = (bx & 15) * 32, grp = bx >> 4, m0 = grp * 64;
        bool odd = (lane & 1) != 0;

        #pragma unroll 1
        for (int t = 0; t < SEQ; t++) {
            const uint32_t* __restrict__ ax = g_Ax[t & 1];
            const uint32_t* __restrict__ hp = g_Hp + (size_t)t * BBHH;

            float acc[2][4][4];
            #pragma unroll
            for (int i = 0; i < 2; i++)
                #pragma unroll
                for (int nt = 0; nt < 4; nt++)
                    #pragma unroll
                    for (int q = 0; q < 4; q++) acc[i][nt][q] = 0.f;

            issue_B64(sbase, tid, j0, 0);  CP_COMMIT();
            loadstore_A64(sm, ax, hp, m0, 0, tid);

            #pragma unroll 1
            for (int c = 0; c < 16; c++) {
                CP_WAIT0();
                __syncthreads();
                if (c + 1 < 16) {
                    issue_B64(sbase + (uint32_t)((c + 1) & 1) * S2_STAGE, tid, j0, (c + 1) * 64);
                    CP_COMMIT();
                    loadstore_A64(sm + ((c + 1) & 1) * S2_STAGE, ax, hp, m0, (c + 1) * 64, tid);
                }
                tile_compute64(sbase + (uint32_t)(c & 1) * S2_STAGE, wm, wn, lane, acc);
            }

            uint32_t* __restrict__ hpn = g_Hp + (size_t)(t + 1) * BBHH;
            uint32_t* __restrict__ axn = g_Ax[(t + 1) & 1];
            #pragma unroll
            for (int i = 0; i < 2; i++)
                #pragma unroll
                for (int nt = 0; nt < 4; nt++) {
                    float s0 = __shfl_xor_sync(0xFFFFFFFFu, acc[i][nt][0], 1);
                    float s1 = __shfl_xor_sync(0xFFFFFFFFu, acc[i][nt][1], 1);
                    float s2 = __shfl_xor_sync(0xFFFFFFFFu, acc[i][nt][2], 1);
                    float s3 = __shfl_xor_sync(0xFFFFFFFFu, acc[i][nt][3], 1);
                    int j = j0 + wn * 8 + nt * 2 + ((lane & 3) >> 1);
                    int m = m0 + wm * 32 + i * 16 + (lane >> 2) + (odd ? 8 : 0);
                    float gi = odd ? s2 : acc[i][nt][0];
                    float gf = odd ? s3 : acc[i][nt][1];
                    float gg = odd ? acc[i][nt][2] : s0;
                    float go = odd ? acc[i][nt][3] : s1;
                    gi += g_bcat[j]; gf += g_bcat[HH + j]; gg += g_bcat[2 * HH + j]; go += g_bcat[3 * HH + j];
                    size_t o = (size_t)m * HH + j;
                    float cn = sigf(gf) * g_c[o] + sigf(gi) * tanhf(gg);
                    g_c[o] = cn;
                    float h = sigf(go) * tanhf(cn);
                    uint32_t p = packf(h);
                    hpn[o] = p;
                    axn[o] = (h > 0.f) ? p : 0u;
                }

            gridbar_grp(grp);   // every step -> gen reaches SEQ
        }
    } else {
        int cta = bx - NCTAS;   // 0..39
        // ---------------- phase 1: num head ----------------
        #pragma unroll 1
        for (int tIdx = 0; tIdx < TILES_PER_NUMCTA; tIdx++) {
            int m0 = (cta * TILES_PER_NUMCTA + tIdx) * 64;
            float s[4] = {0.f, 0.f, 0.f, 0.f};
            #pragma unroll 1
            for (int q = 0; q < 4; q++) {
                int j0 = q * 128;
                float acc[2][4][4];
                #pragma unroll
                for (int i = 0; i < 2; i++)
                    #pragma unroll
                    for (int nt = 0; nt < 4; nt++)
                        #pragma unroll
                        for (int qq = 0; qq < 4; qq++) acc[i][nt][qq] = 0.f;

                numB_issue(sbase, tid, j0, 0); CP_COMMIT();
                num_loadA(sm, E, m0, 0, tid);
                #pragma unroll 1
                for (int c = 0; c < 4; c++) {
                    CP_WAIT0();
                    __syncthreads();
                    if (c + 1 < 4) {
                        numB_issue(sbase + (uint32_t)((c + 1) & 1) * S2_STAGE, tid, j0, (c + 1) * 64);
                        CP_COMMIT();
                        num_loadA(sm + ((c + 1) & 1) * S2_STAGE, E, m0, (c + 1) * 64, tid);
                    }
                    tile_compute64(sbase + (uint32_t)(c & 1) * S2_STAGE, wm, wn, lane, acc);
                }
                #pragma unroll
                for (int i = 0; i < 2; i++)
                    #pragma unroll
                    for (int nt = 0; nt < 4; nt++)
                        #pragma unroll
                        for (int qq = 0; qq < 4; qq++) {
                            int j = j0 + wn * 32 + nt * 8 + (lane & 3) * 2 + (qq & 1);
                            float v = acc[i][nt][qq] + __ldg(&bseq[j]);
                            v = v > 0.f ? v : 0.01f * v;
                            s[i * 2 + (qq >> 1)] += v * __ldg(&w2[j]);
                        }
                __syncthreads();
            }
            #pragma unroll
            for (int k = 0; k < 4; k++) {
                s[k] += __shfl_xor_sync(0xFFFFFFFFu, s[k], 1);
                s[k] += __shfl_xor_sync(0xFFFFFFFFu, s[k], 2);
            }
            float* P = (float*)sm;
            if ((lane & 3) == 0) {
                #pragma unroll
                for (int i = 0; i < 2; i++)
                    #pragma unroll
                    for (int rh = 0; rh < 2; rh++)
                        P[wn * 64 + wm * 32 + i * 16 + rh * 8 + (lane >> 2)] = s[i * 2 + rh];
            }
            __syncthreads();
            if (tid < 64) {
                float v = P[tid] + P[64 + tid] + P[128 + tid] + P[192 + tid] + __ldg(&b2[0]);
                outnum[m0 + tid] = v > 0.f ? v : 0.f;
            }
            __syncthreads();
        }
        // ---------------- phase 2: y projection for t=0..99, gated on per-group gen ----------------
        #pragma unroll 1
        for (int task = cta; task < YTASKS; task += NUMCTAS) {
            int t = task >> 4, mt = task & 15;
            int m0 = mt * 64;
            if (tid == 0) {
                volatile unsigned* vgen = (volatile unsigned*)&g_ggen[mt * 32];
                while (*vgen < (unsigned)(t + 1)) { __nanosleep(256); }
            }
            __syncthreads();
            const uint32_t* __restrict__ hp = g_Hp + (size_t)(t + 1) * BBHH;

            float acc[2][4][4];
            #pragma unroll
            for (int i = 0; i < 2; i++)
                #pragma unroll
                for (int nt = 0; nt < 4; nt++)
                    #pragma unroll
                    for (int q = 0; q < 4; q++) acc[i][nt][q] = 0.f;

            yB_issue(sbase, tid, 0); CP_COMMIT();
            y_loadA(sm, hp, m0, 0, tid);
            #pragma unroll 1
            for (int c = 0; c < 8; c++) {
                CP_WAIT0();
                __syncthreads();
                if (c + 1 < 8) {
                    yB_issue(sbase + (uint32_t)((c + 1) & 1) * S2_STAGE, tid, (c + 1) * 64);
                    CP_COMMIT();
                    y_loadA(sm + ((c + 1) & 1) * S2_STAGE, hp, m0, (c + 1) * 64, tid);
                }
                tile_compute64(sbase + (uint32_t)(c & 1) * S2_STAGE, wm, wn, lane, acc);
            }
            #pragma unroll
            for (int i = 0; i < 2; i++)
                #pragma unroll
                for (int nt = 0; nt < 4; nt++)
                    #pragma unroll
                    for (int q = 0; q < 4; q++) {
                        int o = wn * 32 + nt * 8 + (lane & 3) * 2 + (q & 1);
                        int m = m0 + wm * 32 + i * 16 + (lane >> 2) + (q >> 1) * 8;
                        out_dec[((size_t)m * SEQ + t) * OO + o] = acc[i][nt][q] + __ldg(&bout[o]);
                    }
            __syncthreads();
        }
    }
}

// ======================= prep kernels =======================
__global__ void prep_w(const float* __restrict__ Wih, const float* __restrict__ Whh,
                       const float* __restrict__ bih, const float* __restrict__ bhh,
                       const float* __restrict__ st, const float* __restrict__ Wemb,
                       const float* __restrict__ bemb) {
    int idx = blockIdx.x * blockDim.x + threadIdx.x;
    if (idx < H4 * K2H) {
        int rn = idx / K2H, k = idx % K2H;
        int j = rn >> 2, g = rn & 3;
        int src = g * HH + j;
        float v = (k < HH) ? Wih[src * HH + k] : Whh[src * HH + (k - HH)];
        __nv_bfloat16 h = __float2bfloat16(v);
        g_Wb_hi[idx] = h;
        g_Wb_lo[idx] = __float2bfloat16(v - __bfloat162float(h));
    }
    if (idx < H4) g_bcat[idx] = bih[idx] + bhh[idx];
    if (blockIdx.x < 64) {
        int wid = threadIdx.x >> 5, lane = threadIdx.x & 31;
        int j = blockIdx.x * 8 + wid;
        float4 a = ((const float4*)st)[lane];
        float4 w = *(const float4*)&Wemb[j * OO + lane * 4];
        float s = a.x * w.x + a.y * w.y + a.z * w.z + a.w * w.w;
        #pragma unroll
        for (int o = 16; o; o >>= 1) s += __shfl_xor_sync(0xFFFFFFFFu, s, o);
        if (lane == 0) g_emb[j] = bemb[j] + s;
    }
}
__global__ void prep2W(const float* __restrict__ Wseq, const float* __restrict__ Wout) {
    int i = blockIdx.x * blockDim.x + threadIdx.x;
    if (i < HH * LL) {
        float v = Wseq[i];
        __nv_bfloat16 h = __float2bfloat16(v);
        g_Ws_hi[i] = h;
        g_Ws_lo[i] = __float2bfloat16(v - __bfloat162float(h));
    }
    if (i < OO * HH) {
        float v = Wout[i];
        __nv_bfloat16 h = __float2bfloat16(v);
        g_Wo_hi[i] = h;
        g_Wo_lo[i] = __float2bfloat16(v - __bfloat162float(h));
    }
}

// ======================= init: h0/c0 + Hp slab 0 + Ax seed (round-6 fold) =======================
__global__ void __launch_bounds__(256) init_kernel(
    const float* __restrict__ eh, const float* __restrict__ W1, const float* __restrict__ b1,
    const float* __restrict__ W2, const float* __restrict__ b2) {
    __shared__ float As[64][17], B1s[64][17], B2s[64][17];
    int m0 = blockIdx.y * 64, j0 = blockIdx.x * 64;
    int tid = threadIdx.x, tm = tid >> 4, tj = tid & 15;
    float acc1[4][4] = {}, acc2[4][4] = {};
    for (int k0 = 0; k0 < LL; k0 += 16) {
        int r = tid >> 2, c = (tid & 3) * 4;
        float4 va = *(const float4*)&eh[(m0 + r) * LL + k0 + c];
        As[r][c] = va.x; As[r][c+1] = va.y; As[r][c+2] = va.z; As[r][c+3] = va.w;
        float4 v1 = *(const float4*)&W1[(j0 + r) * LL + k0 + c];
        B1s[r][c] = v1.x; B1s[r][c+1] = v1.y; B1s[r][c+2] = v1.z; B1s[r][c+3] = v1.w;
        float4 v2 = *(const float4*)&W2[(j0 + r) * LL + k0 + c];
        B2s[r][c] = v2.x; B2s[r][c+1] = v2.y; B2s[r][c+2] = v2.z; B2s[r][c+3] = v2.w;
        __syncthreads();
        #pragma unroll
        for (int kk = 0; kk < 16; kk++) {
            float a[4], u[4], v[4];
            #pragma unroll
            for (int i = 0; i < 4; i++) a[i] = As[tm * 4 + i][kk];
            #pragma unroll
            for (int jv = 0; jv < 4; jv++) { u[jv] = B1s[tj + jv * 16][kk]; v[jv] = B2s[tj + jv * 16][kk]; }
            #pragma unroll
            for (int i = 0; i < 4; i++)
                #pragma unroll
                for (int jv = 0; jv < 4; jv++) { acc1[i][jv] += a[i] * u[jv]; acc2[i][jv] += a[i] * v[jv]; }
        }
        __syncthreads();
    }
    #pragma unroll
    for (int i = 0; i < 4; i++)
        #pragma unroll
        for (int jv = 0; jv < 4; jv++) {
            int m = m0 + tm * 4 + i, j = j0 + tj + jv * 16;
            float h0 = acc1[i][jv] + b1[j]; h0 = h0 > 0.f ? h0 : 0.01f * h0;
            float c0 = acc2[i][jv] + b2[j]; c0 = c0 > 0.f ? c0 : 0.01f * c0;
            size_t o = (size_t)m * HH + j;
            g_c[o] = c0;
            g_Hp[o] = packf(h0);
            float e = g_emb[j];
            g_Ax[0][o] = (e > 0.f) ? packf(e) : 0u;
        }
}

__global__ void hc_kernel(float* __restrict__ out_h, float* __restrict__ out_c) {
    int i = blockIdx.x * blockDim.x + threadIdx.x;
    if (i < BBHH) {
        out_h[i] = unpackf(g_Hp[(size_t)SEQ * BBHH + i]);
        out_c[i] = g_c[i];
    }
}

// ======================= launch =======================
extern "C" void kernel_launch(void* const* d_in, const int* in_sizes, int n_in,
                              void* d_out, int out_size) {
    const float* enc_out = (const float*)d_in[0];
    const float* enc_hid = (const float*)d_in[1];
    const float* start   = (const float*)d_in[2];
    const float* W1   = (const float*)d_in[3];
    const float* b1   = (const float*)d_in[4];
    const float* W2   = (const float*)d_in[5];
    const float* b2   = (const float*)d_in[6];
    const float* Wemb = (const float*)d_in[7];
    const float* bemb = (const float*)d_in[8];
    const float* Wih  = (const float*)d_in[9];
    const float* Whh  = (const float*)d_in[10];
    const float* bih  = (const float*)d_in[11];
    const float* bhh  = (const float*)d_in[12];
    const float* Wout = (const float*)d_in[13];
    const float* bout = (const float*)d_in[14];
    const float* Wseq = (const float*)d_in[15];
    const float* bseq = (const float*)d_in[16];
    const float* Wsq2 = (const float*)d_in[17];
    const float* bsq2 = (const float*)d_in[18];
    // d_in[19] = seq_len (constant 100; hardcoded)

    float* out = (float*)d_out;
    float* out_dec = out;                           // [B, SEQ, O]
    float* out_h   = out + (size_t)BB * SEQ * OO;   // [1, B, H]
    float* out_c   = out_h + (size_t)BBHH;          // [1, B, H]
    float* out_num = out_c + (size_t)BBHH;          // [B, TENC, 1]

    cudaFuncSetAttribute(step_persist, cudaFuncAttributeMaxDynamicSharedMemorySize, S2_SMEM);

    prep_w<<<(H4 * K2H + 255) / 256, 256>>>(Wih, Whh, bih, bhh, start, Wemb, bemb);
    prep2W<<<(HH * LL + 255) / 256, 256>>>(Wseq, Wout);
    init_kernel<<<dim3(HH / 64, BB / 64), 256>>>(enc_hid, W1, b1, W2, b2);

    step_persist<<<NCTAS + NUMCTAS, 256, S2_SMEM>>>(enc_out, bseq, Wsq2, bsq2,
                                                     out_num, bout, out_dec);

    hc_kernel<<<(BBHH + 255) / 256, 256>>>(out_h, out_c);
}

// round 17
// speedup vs baseline: 1.3693x; 1.0049x over previous
#include <cuda_runtime.h>
#include <cuda_bf16.h>
#include <math.h>
#include <stdint.h>

// Problem constants (fixed by setup_inputs)
#define BB   1024
#define LL   256
#define HH   512
#define OO   128
#define TENC 200
#define SEQ  100
#define H4   2048
#define K2H  1024
#define BTENC (BB*TENC)
#define BBHH (BB*HH)
#define NCTAS 256
#define NUMCTAS 40
#define TILES_PER_NUMCTA 80   // 3200 M64 num tiles / 40 CTAs
#define YTASKS (SEQ * 16)     // y tiles for t=0..99 (gen reaches 100)

// ======================= helpers =======================
__device__ __forceinline__ uint32_t smem_u32(const void* p) {
    uint32_t a;
    asm("{ .reg .u64 t; cvta.to.shared.u64 t, %1; cvt.u32.u64 %0, t; }" : "=r"(a) : "l"(p));
    return a;
}
__device__ __forceinline__ void ldm_x4(uint32_t* r, uint32_t addr) {
    asm volatile("ldmatrix.sync.aligned.m8n8.x4.shared.b16 {%0,%1,%2,%3}, [%4];"
                 : "=r"(r[0]), "=r"(r[1]), "=r"(r[2]), "=r"(r[3]) : "r"(addr));
}
__device__ __forceinline__ void mma16816(float* d, const uint32_t* a, const uint32_t* b) {
    asm volatile("mma.sync.aligned.m16n8k16.row.col.f32.bf16.bf16.f32 "
                 "{%0,%1,%2,%3}, {%4,%5,%6,%7}, {%8,%9}, {%0,%1,%2,%3};"
                 : "+f"(d[0]), "+f"(d[1]), "+f"(d[2]), "+f"(d[3])
                 : "r"(a[0]), "r"(a[1]), "r"(a[2]), "r"(a[3]), "r"(b[0]), "r"(b[1]));
}
__device__ __forceinline__ void cp16(uint32_t s, const void* g) {
    asm volatile("cp.async.cg.shared.global [%0], [%1], 16;" :: "r"(s), "l"(g));
}
#define CP_COMMIT() asm volatile("cp.async.commit_group;" ::: "memory")
#define CP_WAIT0()  asm volatile("cp.async.wait_group 0;" ::: "memory")

__device__ __forceinline__ uint4 ldcg4(const uint32_t* p) {
    uint4 r;
    asm volatile("ld.global.cg.v4.u32 {%0,%1,%2,%3}, [%4];"
                 : "=r"(r.x), "=r"(r.y), "=r"(r.z), "=r"(r.w) : "l"(p));
    return r;
}
__device__ __forceinline__ void split4(float4 v, uint32_t& h0, uint32_t& h1, uint32_t& l0, uint32_t& l1) {
    __nv_bfloat16 hx = __float2bfloat16(v.x), hy = __float2bfloat16(v.y);
    __nv_bfloat16 hz = __float2bfloat16(v.z), hw = __float2bfloat16(v.w);
    __nv_bfloat16 lx = __float2bfloat16(v.x - __bfloat162float(hx));
    __nv_bfloat16 ly = __float2bfloat16(v.y - __bfloat162float(hy));
    __nv_bfloat16 lz = __float2bfloat16(v.z - __bfloat162float(hz));
    __nv_bfloat16 lw = __float2bfloat16(v.w - __bfloat162float(hw));
    h0 = (uint32_t)__bfloat16_as_ushort(hx) | ((uint32_t)__bfloat16_as_ushort(hy) << 16);
    h1 = (uint32_t)__bfloat16_as_ushort(hz) | ((uint32_t)__bfloat16_as_ushort(hw) << 16);
    l0 = (uint32_t)__bfloat16_as_ushort(lx) | ((uint32_t)__bfloat16_as_ushort(ly) << 16);
    l1 = (uint32_t)__bfloat16_as_ushort(lz) | ((uint32_t)__bfloat16_as_ushort(lw) << 16);
}
__device__ __forceinline__ uint32_t packf(float h) {
    __nv_bfloat16 hh = __float2bfloat16(h);
    __nv_bfloat16 hl = __float2bfloat16(h - __bfloat162float(hh));
    return (uint32_t)__bfloat16_as_ushort(hh) | ((uint32_t)__bfloat16_as_ushort(hl) << 16);
}
__device__ __forceinline__ float unpackf(uint32_t p) {
    __nv_bfloat16 hi = __ushort_as_bfloat16((unsigned short)(p & 0xFFFFu));
    __nv_bfloat16 lo = __ushort_as_bfloat16((unsigned short)(p >> 16));
    return __bfloat162float(hi) + __bfloat162float(lo);
}
__device__ __forceinline__ float sigf(float x) { return 1.f / (1.f + __expf(-x)); }

// ======================= device scratch =======================
__device__ __align__(16) uint32_t g_Hp[(size_t)(SEQ + 1) * BBHH]; // packed h history; slab 0 = h0
__device__ __align__(16) uint32_t g_Ax[2][BBHH];                  // packed relu(x) side, dbl-buffered
__device__ __align__(16) float g_c[BBHH];
__device__ __align__(16) float g_emb[HH];
__device__ __align__(16) float g_bcat[H4];                        // gate-major [g*HH + j]
__device__ __align__(16) __nv_bfloat16 g_Wb_hi[(size_t)H4 * K2H]; // interleaved rows n'=j*4+g
__device__ __align__(16) __nv_bfloat16 g_Wb_lo[(size_t)H4 * K2H];
__device__ __align__(16) __nv_bfloat16 g_Ws_hi[HH * LL];          // Wseq split [j][k]
__device__ __align__(16) __nv_bfloat16 g_Ws_lo[HH * LL];
__device__ __align__(16) __nv_bfloat16 g_Wo_hi[OO * HH];          // Wout split [o][k]
__device__ __align__(16) __nv_bfloat16 g_Wo_lo[OO * HH];
__device__ unsigned g_gcnt[16 * 32];   // per-m-group barrier counters, 128B-strided
__device__ unsigned g_ggen[16 * 32];   // per-m-group generation

// ======================= per-m-group barrier (16 CTAs each) =======================
__device__ __forceinline__ void gridbar_grp(int grp) {
    __syncthreads();
    if (threadIdx.x == 0) {
        __threadfence();
        volatile unsigned* vgen = (volatile unsigned*)&g_ggen[grp * 32];
        unsigned gen = *vgen;
        if (atomicAdd(&g_gcnt[grp * 32], 1u) == 15u) {
            g_gcnt[grp * 32] = 0u;
            __threadfence();
            atomicAdd(&g_ggen[grp * 32], 1u);
        } else {
            while (*vgen == gen) { __nanosleep(32); }
        }
    }
    __syncthreads();
}

// ======================= M64/K64 2-stage machinery =======================
// stage: A_hi[64][144B] @0, A_lo @9216, B_hi[128][144B] @18432, B_lo @36864; stage = 55296.
#define S2_ALO   9216
#define S2_BHI   18432
#define S2_BLOD  18432
#define S2_STAGE 55296
#define S2_SMEM  (2 * S2_STAGE)

__device__ __forceinline__ void tile_compute64(uint32_t sa, int wm, int wn, int lane, float acc[2][4][4]) {
    #pragma unroll
    for (int kk = 0; kk < 64; kk += 16) {
        uint32_t ah[2][4], al[2][4], bh[2][4], bl[2][4];
        #pragma unroll
        for (int i = 0; i < 2; i++) {
            uint32_t ad = sa + (uint32_t)(wm * 32 + i * 16 + (lane & 15)) * 144
                        + (uint32_t)(kk + (lane >> 4) * 8) * 2;
            ldm_x4(ah[i], ad);
            ldm_x4(al[i], ad + S2_ALO);
        }
        #pragma unroll
        for (int s = 0; s < 2; s++) {
            uint32_t bd = sa + S2_BHI + (uint32_t)(wn * 32 + s * 16 + (lane >> 4) * 8 + (lane & 7)) * 144
                        + (uint32_t)(kk + ((lane >> 3) & 1) * 8) * 2;
            ldm_x4(bh[s], bd);
            ldm_x4(bl[s], bd + S2_BLOD);
        }
        #pragma unroll
        for (int i = 0; i < 2; i++)
            #pragma unroll
            for (int nt = 0; nt < 4; nt++)
                mma16816(acc[i][nt], ah[i], &bh[nt >> 1][(nt & 1) * 2]);
        #pragma unroll
        for (int i = 0; i < 2; i++)
            #pragma unroll
            for (int nt = 0; nt < 4; nt++)
                mma16816(acc[i][nt], ah[i], &bl[nt >> 1][(nt & 1) * 2]);
        #pragma unroll
        for (int i = 0; i < 2; i++)
            #pragma unroll
            for (int nt = 0; nt < 4; nt++)
                mma16816(acc[i][nt], al[i], &bh[nt >> 1][(nt & 1) * 2]);
    }
}

// --- step loaders (round-11 proven) ---
__device__ __forceinline__ void loadstore_A64(char* base,
                                              const uint32_t* __restrict__ ax,
                                              const uint32_t* __restrict__ hp,
                                              int m0, int k0, int tid) {
    #pragma unroll
    for (int i = 0; i < 4; i++) {
        int idx = tid + i * 256, r = idx >> 4, cg = idx & 15;
        int gk = k0 + cg * 4;
        const uint32_t* src = (gk < HH) ? (ax + (size_t)(m0 + r) * HH + gk)
                                        : (hp + (size_t)(m0 + r) * HH + (gk - HH));
        uint4 P = ldcg4(src);
        uint32_t h0 = __byte_perm(P.x, P.y, 0x5410);
        uint32_t h1 = __byte_perm(P.z, P.w, 0x5410);
        uint32_t l0 = __byte_perm(P.x, P.y, 0x7632);
        uint32_t l1 = __byte_perm(P.z, P.w, 0x7632);
        uint32_t off = (uint32_t)r * 144 + (uint32_t)cg * 8;
        *(uint2*)(base + off) = make_uint2(h0, h1);
        *(uint2*)(base + S2_ALO + off) = make_uint2(l0, l1);
    }
}
__device__ __forceinline__ void issue_B64(uint32_t sb, int tid, int j0, int k0) {
    #pragma unroll
    for (int i = 0; i < 8; i++) {
        int idx = tid + i * 256;
        int half = idx >> 10;
        int w = idx & 1023;
        int rr = w >> 3, cc = w & 7;
        uint32_t so = (uint32_t)rr * 144 + (uint32_t)cc * 16;
        const __nv_bfloat16* src = half ? g_Wb_lo : g_Wb_hi;
        cp16(sb + S2_BHI + (uint32_t)half * S2_BLOD + so,
             src + (size_t)(j0 * 4 + rr) * K2H + k0 + cc * 8);
    }
}

// --- num loaders: A = fp32 E split in-kernel; B = pre-split Ws via cp.async ---
__device__ __forceinline__ void num_loadA(char* base, const float* __restrict__ E,
                                          int m0, int k0, int tid) {
    #pragma unroll
    for (int i = 0; i < 4; i++) {
        int idx = tid + i * 256, r = idx >> 4, cg = idx & 15;
        float4 v = __ldg((const float4*)&E[(size_t)(m0 + r) * LL + k0 + cg * 4]);
        uint32_t h0, h1, l0, l1;
        split4(v, h0, h1, l0, l1);
        uint32_t off = (uint32_t)r * 144 + (uint32_t)cg * 8;
        *(uint2*)(base + off) = make_uint2(h0, h1);
        *(uint2*)(base + S2_ALO + off) = make_uint2(l0, l1);
    }
}
__device__ __forceinline__ void numB_issue(uint32_t sb, int tid, int j0, int k0) {
    #pragma unroll
    for (int i = 0; i < 8; i++) {
        int idx = tid + i * 256;
        int half = idx >> 10;
        int w = idx & 1023;
        int rr = w >> 3, cc = w & 7;
        uint32_t so = (uint32_t)rr * 144 + (uint32_t)cc * 16;
        const __nv_bfloat16* src = half ? g_Ws_lo : g_Ws_hi;
        cp16(sb + S2_BHI + (uint32_t)half * S2_BLOD + so,
             src + (size_t)(j0 + rr) * LL + k0 + cc * 8);
    }
}

// --- y loaders: A = packed h slab; B = pre-split Wout ---
__device__ __forceinline__ void y_loadA(char* base, const uint32_t* __restrict__ hp,
                                        int m0, int k0, int tid) {
    #pragma unroll
    for (int i = 0; i < 4; i++) {
        int idx = tid + i * 256, r = idx >> 4, cg = idx & 15;
        uint4 P = ldcg4(hp + (size_t)(m0 + r) * HH + k0 + cg * 4);
        uint32_t h0 = __byte_perm(P.x, P.y, 0x5410);
        uint32_t h1 = __byte_perm(P.z, P.w, 0x5410);
        uint32_t l0 = __byte_perm(P.x, P.y, 0x7632);
        uint32_t l1 = __byte_perm(P.z, P.w, 0x7632);
        uint32_t off = (uint32_t)r * 144 + (uint32_t)cg * 8;
        *(uint2*)(base + off) = make_uint2(h0, h1);
        *(uint2*)(base + S2_ALO + off) = make_uint2(l0, l1);
    }
}
__device__ __forceinline__ void yB_issue(uint32_t sb, int tid, int k0) {
    #pragma unroll
    for (int i = 0; i < 8; i++) {
        int idx = tid + i * 256;
        int half = idx >> 10;
        int w = idx & 1023;
        int rr = w >> 3, cc = w & 7;
        uint32_t so = (uint32_t)rr * 144 + (uint32_t)cc * 16;
        const __nv_bfloat16* src = half ? g_Wo_lo : g_Wo_hi;
        cp16(sb + S2_BHI + (uint32_t)half * S2_BLOD + so,
             src + (size_t)rr * HH + k0 + cc * 8);
    }
}

// ======================= persistent kernel =======================
__global__ void __launch_bounds__(256, 2) step_persist(
    const float* __restrict__ E, const float* __restrict__ bseq,
    const float* __restrict__ w2, const float* __restrict__ b2,
    float* __restrict__ outnum, const float* __restrict__ bout,
    float* __restrict__ out_dec) {
    extern __shared__ char sm[];
    uint32_t sbase = smem_u32(sm);
    int tid = threadIdx.x, lane = tid & 31, wid = tid >> 5;
    int wm = wid & 1, wn = wid >> 1;
    int bx = blockIdx.x;

    if (bx < NCTAS) {
        // ---------------- LSTM path; barrier is per-m-group (16 CTAs), every step ----------------
        int j0 = (bx & 15) * 32, grp = bx >> 4, m0 = grp * 64;
        bool odd = (lane & 1) != 0;

        #pragma unroll 1
        for (int t = 0; t < SEQ; t++) {
            const uint32_t* __restrict__ ax = g_Ax[t & 1];
            const uint32_t* __restrict__ hp = g_Hp + (size_t)t * BBHH;

            float acc[2][4][4];
            #pragma unroll
            for (int i = 0; i < 2; i++)
                #pragma unroll
                for (int nt = 0; nt < 4; nt++)
                    #pragma unroll
                    for (int q = 0; q < 4; q++) acc[i][nt][q] = 0.f;

            issue_B64(sbase, tid, j0, 0);  CP_COMMIT();
            loadstore_A64(sm, ax, hp, m0, 0, tid);

            #pragma unroll 1
            for (int c = 0; c < 16; c++) {
                CP_WAIT0();
                __syncthreads();
                if (c + 1 < 16) {
                    issue_B64(sbase + (uint32_t)((c + 1) & 1) * S2_STAGE, tid, j0, (c + 1) * 64);
                    CP_COMMIT();
                    loadstore_A64(sm + ((c + 1) & 1) * S2_STAGE, ax, hp, m0, (c + 1) * 64, tid);
                }
                tile_compute64(sbase + (uint32_t)(c & 1) * S2_STAGE, wm, wn, lane, acc);
            }

            uint32_t* __restrict__ hpn = g_Hp + (size_t)(t + 1) * BBHH;
            uint32_t* __restrict__ axn = g_Ax[(t + 1) & 1];
            #pragma unroll
            for (int i = 0; i < 2; i++)
                #pragma unroll
                for (int nt = 0; nt < 4; nt++) {
                    float s0 = __shfl_xor_sync(0xFFFFFFFFu, acc[i][nt][0], 1);
                    float s1 = __shfl_xor_sync(0xFFFFFFFFu, acc[i][nt][1], 1);
                    float s2 = __shfl_xor_sync(0xFFFFFFFFu, acc[i][nt][2], 1);
                    float s3 = __shfl_xor_sync(0xFFFFFFFFu, acc[i][nt][3], 1);
                    int j = j0 + wn * 8 + nt * 2 + ((lane & 3) >> 1);
                    int m = m0 + wm * 32 + i * 16 + (lane >> 2) + (odd ? 8 : 0);
                    float gi = odd ? s2 : acc[i][nt][0];
                    float gf = odd ? s3 : acc[i][nt][1];
                    float gg = odd ? acc[i][nt][2] : s0;
                    float go = odd ? acc[i][nt][3] : s1;
                    gi += g_bcat[j]; gf += g_bcat[HH + j]; gg += g_bcat[2 * HH + j]; go += g_bcat[3 * HH + j];
                    size_t o = (size_t)m * HH + j;
                    float cn = sigf(gf) * g_c[o] + sigf(gi) * tanhf(gg);
                    g_c[o] = cn;
                    float h = sigf(go) * tanhf(cn);
                    uint32_t p = packf(h);
                    hpn[o] = p;
                    axn[o] = (h > 0.f) ? p : 0u;
                }

            gridbar_grp(grp);   // every step -> gen reaches SEQ
        }
    } else {
        int cta = bx - NCTAS;   // 0..39
        // ---------------- phase 1: num head ----------------
        #pragma unroll 1
        for (int tIdx = 0; tIdx < TILES_PER_NUMCTA; tIdx++) {
            int m0 = (cta * TILES_PER_NUMCTA + tIdx) * 64;
            float s[4] = {0.f, 0.f, 0.f, 0.f};
            #pragma unroll 1
            for (int q = 0; q < 4; q++) {
                int j0 = q * 128;
                float acc[2][4][4];
                #pragma unroll
                for (int i = 0; i < 2; i++)
                    #pragma unroll
                    for (int nt = 0; nt < 4; nt++)
                        #pragma unroll
                        for (int qq = 0; qq < 4; qq++) acc[i][nt][qq] = 0.f;

                numB_issue(sbase, tid, j0, 0); CP_COMMIT();
                num_loadA(sm, E, m0, 0, tid);
                #pragma unroll 1
                for (int c = 0; c < 4; c++) {
                    CP_WAIT0();
                    __syncthreads();
                    if (c + 1 < 4) {
                        numB_issue(sbase + (uint32_t)((c + 1) & 1) * S2_STAGE, tid, j0, (c + 1) * 64);
                        CP_COMMIT();
                        num_loadA(sm + ((c + 1) & 1) * S2_STAGE, E, m0, (c + 1) * 64, tid);
                    }
                    tile_compute64(sbase + (uint32_t)(c & 1) * S2_STAGE, wm, wn, lane, acc);
                }
                #pragma unroll
                for (int i = 0; i < 2; i++)
                    #pragma unroll
                    for (int nt = 0; nt < 4; nt++)
                        #pragma unroll
                        for (int qq = 0; qq < 4; qq++) {
                            int j = j0 + wn * 32 + nt * 8 + (lane & 3) * 2 + (qq & 1);
                            float v = acc[i][nt][qq] + __ldg(&bseq[j]);
                            v = v > 0.f ? v : 0.01f * v;
                            s[i * 2 + (qq >> 1)] += v * __ldg(&w2[j]);
                        }
                __syncthreads();
            }
            #pragma unroll
            for (int k = 0; k < 4; k++) {
                s[k] += __shfl_xor_sync(0xFFFFFFFFu, s[k], 1);
                s[k] += __shfl_xor_sync(0xFFFFFFFFu, s[k], 2);
            }
            float* P = (float*)sm;
            if ((lane & 3) == 0) {
                #pragma unroll
                for (int i = 0; i < 2; i++)
                    #pragma unroll
                    for (int rh = 0; rh < 2; rh++)
                        P[wn * 64 + wm * 32 + i * 16 + rh * 8 + (lane >> 2)] = s[i * 2 + rh];
            }
            __syncthreads();
            if (tid < 64) {
                float v = P[tid] + P[64 + tid] + P[128 + tid] + P[192 + tid] + __ldg(&b2[0]);
                outnum[m0 + tid] = v > 0.f ? v : 0.f;
            }
            __syncthreads();
        }
        // ---------------- phase 2: y projection for t=0..99, gated on per-group gen ----------------
        #pragma unroll 1
        for (int task = cta; task < YTASKS; task += NUMCTAS) {
            int t = task >> 4, mt = task & 15;
            int m0 = mt * 64;
            if (tid == 0) {
                volatile unsigned* vgen = (volatile unsigned*)&g_ggen[mt * 32];
                while (*vgen < (unsigned)(t + 1)) { __nanosleep(256); }
            }
            __syncthreads();
            const uint32_t* __restrict__ hp = g_Hp + (size_t)(t + 1) * BBHH;

            float acc[2][4][4];
            #pragma unroll
            for (int i = 0; i < 2; i++)
                #pragma unroll
                for (int nt = 0; nt < 4; nt++)
                    #pragma unroll
                    for (int q = 0; q < 4; q++) acc[i][nt][q] = 0.f;

            yB_issue(sbase, tid, 0); CP_COMMIT();
            y_loadA(sm, hp, m0, 0, tid);
            #pragma unroll 1
            for (int c = 0; c < 8; c++) {
                CP_WAIT0();
                __syncthreads();
                if (c + 1 < 8) {
                    yB_issue(sbase + (uint32_t)((c + 1) & 1) * S2_STAGE, tid, (c + 1) * 64);
                    CP_COMMIT();
                    y_loadA(sm + ((c + 1) & 1) * S2_STAGE, hp, m0, (c + 1) * 64, tid);
                }
                tile_compute64(sbase + (uint32_t)(c & 1) * S2_STAGE, wm, wn, lane, acc);
            }
            #pragma unroll
            for (int i = 0; i < 2; i++)
                #pragma unroll
                for (int nt = 0; nt < 4; nt++)
                    #pragma unroll
                    for (int q = 0; q < 4; q++) {
                        int o = wn * 32 + nt * 8 + (lane & 3) * 2 + (q & 1);
                        int m = m0 + wm * 32 + i * 16 + (lane >> 2) + (q >> 1) * 8;
                        out_dec[((size_t)m * SEQ + t) * OO + o] = acc[i][nt][q] + __ldg(&bout[o]);
                    }
            __syncthreads();
        }
    }
}

// ======================= prep kernels =======================
__global__ void prep_w(const float* __restrict__ Wih, const float* __restrict__ Whh,
                       const float* __restrict__ bih, const float* __restrict__ bhh,
                       const float* __restrict__ st, const float* __restrict__ Wemb,
                       const float* __restrict__ bemb) {
    int idx = blockIdx.x * blockDim.x + threadIdx.x;
    if (idx < H4 * K2H) {
        int rn = idx / K2H, k = idx % K2H;
        int j = rn >> 2, g = rn & 3;
        int src = g * HH + j;
        float v = (k < HH) ? Wih[src * HH + k] : Whh[src * HH + (k - HH)];
        __nv_bfloat16 h = __float2bfloat16(v);
        g_Wb_hi[idx] = h;
        g_Wb_lo[idx] = __float2bfloat16(v - __bfloat162float(h));
    }
    if (idx < H4) g_bcat[idx] = bih[idx] + bhh[idx];
    if (blockIdx.x < 64) {
        int wid = threadIdx.x >> 5, lane = threadIdx.x & 31;
        int j = blockIdx.x * 8 + wid;
        float4 a = ((const float4*)st)[lane];
        float4 w = *(const float4*)&Wemb[j * OO + lane * 4];
        float s = a.x * w.x + a.y * w.y + a.z * w.z + a.w * w.w;
        #pragma unroll
        for (int o = 16; o; o >>= 1) s += __shfl_xor_sync(0xFFFFFFFFu, s, o);
        if (lane == 0) g_emb[j] = bemb[j] + s;
    }
}
__global__ void prep2W(const float* __restrict__ Wseq, const float* __restrict__ Wout) {
    int i = blockIdx.x * blockDim.x + threadIdx.x;
    if (i < HH * LL) {
        float v = Wseq[i];
        __nv_bfloat16 h = __float2bfloat16(v);
        g_Ws_hi[i] = h;
        g_Ws_lo[i] = __float2bfloat16(v - __bfloat162float(h));
    }
    if (i < OO * HH) {
        float v = Wout[i];
        __nv_bfloat16 h = __float2bfloat16(v);
        g_Wo_hi[i] = h;
        g_Wo_lo[i] = __float2bfloat16(v - __bfloat162float(h));
    }
}

// ======================= init: h0/c0 + Hp slab 0 + Ax seed (round-6 fold) =======================
__global__ void __launch_bounds__(256) init_kernel(
    const float* __restrict__ eh, const float* __restrict__ W1, const float* __restrict__ b1,
    const float* __restrict__ W2, const float* __restrict__ b2) {
    __shared__ float As[64][17], B1s[64][17], B2s[64][17];
    int m0 = blockIdx.y * 64, j0 = blockIdx.x * 64;
    int tid = threadIdx.x, tm = tid >> 4, tj = tid & 15;
    float acc1[4][4] = {}, acc2[4][4] = {};
    for (int k0 = 0; k0 < LL; k0 += 16) {
        int r = tid >> 2, c = (tid & 3) * 4;
        float4 va = *(const float4*)&eh[(m0 + r) * LL + k0 + c];
        As[r][c] = va.x; As[r][c+1] = va.y; As[r][c+2] = va.z; As[r][c+3] = va.w;
        float4 v1 = *(const float4*)&W1[(j0 + r) * LL + k0 + c];
        B1s[r][c] = v1.x; B1s[r][c+1] = v1.y; B1s[r][c+2] = v1.z; B1s[r][c+3] = v1.w;
        float4 v2 = *(const float4*)&W2[(j0 + r) * LL + k0 + c];
        B2s[r][c] = v2.x; B2s[r][c+1] = v2.y; B2s[r][c+2] = v2.z; B2s[r][c+3] = v2.w;
        __syncthreads();
        #pragma unroll
        for (int kk = 0; kk < 16; kk++) {
            float a[4], u[4], v[4];
            #pragma unroll
            for (int i = 0; i < 4; i++) a[i] = As[tm * 4 + i][kk];
            #pragma unroll
            for (int jv = 0; jv < 4; jv++) { u[jv] = B1s[tj + jv * 16][kk]; v[jv] = B2s[tj + jv * 16][kk]; }
            #pragma unroll
            for (int i = 0; i < 4; i++)
                #pragma unroll
                for (int jv = 0; jv < 4; jv++) { acc1[i][jv] += a[i] * u[jv]; acc2[i][jv] += a[i] * v[jv]; }
        }
        __syncthreads();
    }
    #pragma unroll
    for (int i = 0; i < 4; i++)
        #pragma unroll
        for (int jv = 0; jv < 4; jv++) {
            int m = m0 + tm * 4 + i, j = j0 + tj + jv * 16;
            float h0 = acc1[i][jv] + b1[j]; h0 = h0 > 0.f ? h0 : 0.01f * h0;
            float c0 = acc2[i][jv] + b2[j]; c0 = c0 > 0.f ? c0 : 0.01f * c0;
            size_t o = (size_t)m * HH + j;
            g_c[o] = c0;
            g_Hp[o] = packf(h0);
            float e = g_emb[j];
            g_Ax[0][o] = (e > 0.f) ? packf(e) : 0u;
        }
}

__global__ void hc_kernel(float* __restrict__ out_h, float* __restrict__ out_c) {
    int i = blockIdx.x * blockDim.x + threadIdx.x;
    if (i < BBHH) {
        out_h[i] = unpackf(g_Hp[(size_t)SEQ * BBHH + i]);
        out_c[i] = g_c[i];
    }
}

// ======================= launch =======================
extern "C" void kernel_launch(void* const* d_in, const int* in_sizes, int n_in,
                              void* d_out, int out_size) {
    const float* enc_out = (const float*)d_in[0];
    const float* enc_hid = (const float*)d_in[1];
    const float* start   = (const float*)d_in[2];
    const float* W1   = (const float*)d_in[3];
    const float* b1   = (const float*)d_in[4];
    const float* W2   = (const float*)d_in[5];
    const float* b2   = (const float*)d_in[6];
    const float* Wemb = (const float*)d_in[7];
    const float* bemb = (const float*)d_in[8];
    const float* Wih  = (const float*)d_in[9];
    const float* Whh  = (const float*)d_in[10];
    const float* bih  = (const float*)d_in[11];
    const float* bhh  = (const float*)d_in[12];
    const float* Wout = (const float*)d_in[13];
    const float* bout = (const float*)d_in[14];
    const float* Wseq = (const float*)d_in[15];
    const float* bseq = (const float*)d_in[16];
    const float* Wsq2 = (const float*)d_in[17];
    const float* bsq2 = (const float*)d_in[18];
    // d_in[19] = seq_len (constant 100; hardcoded)

    float* out = (float*)d_out;
    float* out_dec = out;                           // [B, SEQ, O]
    float* out_h   = out + (size_t)BB * SEQ * OO;   // [1, B, H]
    float* out_c   = out_h + (size_t)BBHH;          // [1, B, H]
    float* out_num = out_c + (size_t)BBHH;          // [B, TENC, 1]

    cudaFuncSetAttribute(step_persist, cudaFuncAttributeMaxDynamicSharedMemorySize, S2_SMEM);

    prep_w<<<(H4 * K2H + 255) / 256, 256>>>(Wih, Whh, bih, bhh, start, Wemb, bemb);
    prep2W<<<(HH * LL + 255) / 256, 256>>>(Wseq, Wout);
    init_kernel<<<dim3(HH / 64, BB / 64), 256>>>(enc_hid, W1, b1, W2, b2);

    step_persist<<<NCTAS + NUMCTAS, 256, S2_SMEM>>>(enc_out, bseq, Wsq2, bsq2,
                                                     out_num, bout, out_dec);

    hc_kernel<<<(BBHH + 255) / 256, 256>>>(out_h, out_c);
}